// round 7
// baseline (speedup 1.0000x reference)
#include <cuda_runtime.h>
#include <cuda_bf16.h>
#include <math.h>
#include <stdint.h>

#define BB    256
#define NNODE 100
#define EE    1600
#define ESL   1700
#define FF    2048
#define HH    512
#define DD    256
#define PP    1024
#define KTOP  50
#define BN    (BB*NNODE)   // 25600

// ---------------- scratch ----------------
__device__ __align__(16) __nv_bfloat16 g_W1hi[(size_t)HH*FF];   // W_gcn^T split [512,2048]
__device__ __align__(16) __nv_bfloat16 g_W1lo[(size_t)HH*FF];
__device__ __align__(16) float g_H1[(size_t)BN*HH];             // X @ W_gcn (fp32)
__device__ __align__(16) float g_h [(size_t)BN*HH];             // relu(GCN out), fp32
__device__ float g_wasrc[HH];
__device__ float g_wadst[HH];
__device__ float g_dinv[BN];
__device__ float g_asrc[BN];
__device__ float g_adst[BN];
__device__ float g_alpha[(size_t)BB*ESL];
__device__ int   g_esrc[(size_t)BB*ESL];
__device__ int   g_edst[(size_t)BB*ESL];
__device__ int   g_doff[BB*(NNODE+1)];
__device__ int   g_soff[BB*(NNODE+1)];
__device__ int   g_deid[(size_t)BB*ESL];
__device__ int   g_seid[(size_t)BB*ESL];
__device__ float g_scores[BN];
__device__ int   g_topk[KTOP];

// ---------------- helpers ----------------
__device__ __forceinline__ uint32_t smem_u32(const void* p) {
    uint32_t a;
    asm("{ .reg .u64 t; cvta.to.shared.u64 t, %1; cvt.u32.u64 %0, t; }" : "=r"(a) : "l"(p));
    return a;
}
__device__ __forceinline__ void cp_async16(uint32_t dst, const void* src) {
    asm volatile("cp.async.cg.shared.global [%0], [%1], 16;" :: "r"(dst), "l"(src) : "memory");
}
__device__ __forceinline__ void cp_commit() {
    asm volatile("cp.async.commit_group;" ::: "memory");
}
__device__ __forceinline__ void cp_wait0() {
    asm volatile("cp.async.wait_group 0;" ::: "memory");
}
__device__ __forceinline__ void cp_wait2() {
    asm volatile("cp.async.wait_group 2;" ::: "memory");
}
__device__ __forceinline__ void ldsm_x4(uint32_t& r0, uint32_t& r1, uint32_t& r2, uint32_t& r3, uint32_t a) {
    asm volatile("ldmatrix.sync.aligned.m8n8.x4.shared.b16 {%0,%1,%2,%3}, [%4];"
                 : "=r"(r0), "=r"(r1), "=r"(r2), "=r"(r3) : "r"(a));
}
__device__ __forceinline__ void mma_bf16(float* c, const uint32_t* a, uint32_t b0, uint32_t b1) {
    asm volatile(
        "mma.sync.aligned.m16n8k16.row.col.f32.bf16.bf16.f32 "
        "{%0,%1,%2,%3}, {%4,%5,%6,%7}, {%8,%9}, {%0,%1,%2,%3};"
        : "+f"(c[0]), "+f"(c[1]), "+f"(c[2]), "+f"(c[3])
        : "r"(a[0]), "r"(a[1]), "r"(a[2]), "r"(a[3]), "r"(b0), "r"(b1));
}
__device__ __forceinline__ void split2(float v, __nv_bfloat16& h, __nv_bfloat16& l) {
    h = __float2bfloat16_rn(v);
    l = __float2bfloat16_rn(v - __bfloat162float(h));
}
// pack (x0 -> low, x1 -> high) as bf16x2 hi part + residual lo part
__device__ __forceinline__ void splitpair(float x0, float x1, uint32_t& hi, uint32_t& lo) {
    asm("cvt.rn.bf16x2.f32 %0, %1, %2;" : "=r"(hi) : "f"(x1), "f"(x0));
    __nv_bfloat162 b = *reinterpret_cast<__nv_bfloat162*>(&hi);
    float h0 = __bfloat162float(b.x), h1 = __bfloat162float(b.y);
    asm("cvt.rn.bf16x2.f32 %0, %1, %2;" : "=r"(lo) : "f"(x1 - h1), "f"(x0 - h0));
}

// ---------------- weight transpose + split ----------------
__global__ void splitT_k(const float* __restrict__ W, __nv_bfloat16* __restrict__ Thi,
                         __nv_bfloat16* __restrict__ Tlo, int R, int C) {
    __shared__ float tile[32][33];
    int rb = blockIdx.x * 32, cb = blockIdx.y * 32;
    int tx = threadIdx.x, ty = threadIdx.y;
#pragma unroll
    for (int i = 0; i < 4; i++)
        tile[ty + i * 8][tx] = W[(size_t)(rb + ty + i * 8) * C + cb + tx];
    __syncthreads();
#pragma unroll
    for (int i = 0; i < 4; i++) {
        float v = tile[tx][ty + i * 8];
        __nv_bfloat16 h, l; split2(v, h, l);
        size_t o = (size_t)(cb + ty + i * 8) * R + rb + tx;
        Thi[o] = h; Tlo[o] = l;
    }
}

// ---------------- fused-split mma.sync GEMM, 512 threads ----------------
// C[M,N] = A @ Bt^T : A=[M,K] fp32 row-major (split to bf16 hi/lo in-register),
// Bt=[N,K] bf16 hi/lo row-major. CTA 128x128, 16 warps = 4(M) x 4(N), warp 32x32.
// 4-stage cp.async pipeline, K-chunk 32 per stage.
#define ARS      160                    // fp32 A row: 32 floats = 128B + 32B pad
#define BRS      80                     // bf16 B row: 32 bf16 = 64B + 16B pad
#define A_TILE   (128*ARS)              // 20480
#define B_TILE   (128*BRS)              // 10240
#define STAGE_B  (A_TILE + 2*B_TILE)    // 40960
#define NSTAGE   4
__global__ __launch_bounds__(512) void mma_gemm(
    const float* __restrict__ A,
    const __nv_bfloat16* __restrict__ Bhi, const __nv_bfloat16* __restrict__ Blo,
    float* __restrict__ C, int M, int N, int K)
{
    extern __shared__ __align__(16) char smem[];
    uint32_t sb = smem_u32(smem);
    int t = threadIdx.x;
    int lane = t & 31, w = t >> 5;
    int row0 = blockIdx.y * 128, col0 = blockIdx.x * 128;
    int wr = (w & 3) * 32, wn = (w >> 2) * 32;

    // A loader: 1024 chunks (128 rows x 8x16B of fp32); 2 per thread
    uint32_t aso[2]; int aqr[2], aqc[2];
#pragma unroll
    for (int i = 0; i < 2; i++) {
        int q = t + 512 * i;
        aqr[i] = q >> 3; aqc[i] = q & 7;
        aso[i] = (uint32_t)(aqr[i] * ARS + aqc[i] * 16);
    }
    // B loader: 512 chunks per matrix (128 rows x 4x16B of bf16); 1 per thread
    int bqr = t >> 2, bqc = t & 3;
    uint32_t bso = (uint32_t)(bqr * BRS + bqc * 16);

    // A fragment LDS addresses (fp32)
    uint32_t a_base[2];
#pragma unroll
    for (int blk = 0; blk < 2; blk++)
        a_base[blk] = (uint32_t)((wr + blk * 16 + (lane >> 2)) * ARS + (lane & 3) * 8);

    // B ldmatrix addresses (2 groups of n16)
    uint32_t boff[2];
#pragma unroll
    for (int g = 0; g < 2; g++) {
        int quad = lane >> 3;
        int rB = wn + g * 16 + (lane & 7) + (quad >> 1) * 8;
        boff[g] = (uint32_t)(rB * BRS + (quad & 1) * 16);
    }

    float c[2][4][4];
#pragma unroll
    for (int i = 0; i < 2; i++)
#pragma unroll
        for (int jn = 0; jn < 4; jn++)
#pragma unroll
            for (int e = 0; e < 4; e++) c[i][jn][e] = 0.f;

    int nIter = K >> 5;

    auto load_stage = [&](int s) {
        uint32_t st = sb + (s & 3) * STAGE_B;
        int k0 = s << 5;
#pragma unroll
        for (int i = 0; i < 2; i++)
            cp_async16(st + aso[i], A + (size_t)(row0 + aqr[i]) * K + k0 + aqc[i] * 4);
        cp_async16(st + A_TILE + bso,          Bhi + (size_t)(col0 + bqr) * K + k0 + bqc * 8);
        cp_async16(st + A_TILE + B_TILE + bso, Blo + (size_t)(col0 + bqr) * K + k0 + bqc * 8);
    };

    load_stage(0); cp_commit();
    load_stage(1); cp_commit();
    load_stage(2); cp_commit();

    for (int it = 0; it < nIter; it++) {
        cp_wait2();
        __syncthreads();

        uint32_t st = sb + (it & 3) * STAGE_B;
        uint32_t sA = st, sBh = st + A_TILE, sBl = st + B_TILE + A_TILE;

#pragma unroll
        for (int j = 0; j < 2; j++) {     // two k16 halves
            uint32_t ah[2][4], al[2][4];
#pragma unroll
            for (int blk = 0; blk < 2; blk++) {
                uint32_t base = sA + a_base[blk] + j * 64;
#pragma unroll
                for (int part = 0; part < 2; part++) {
#pragma unroll
                    for (int rr = 0; rr < 2; rr++) {
                        float2 v;
                        asm volatile("ld.shared.v2.f32 {%0,%1}, [%2];"
                                     : "=f"(v.x), "=f"(v.y)
                                     : "r"(base + part * 32 + rr * (8 * ARS)));
                        int idx = part * 2 + rr;
                        splitpair(v.x, v.y, ah[blk][idx], al[blk][idx]);
                    }
                }
            }
#pragma unroll
            for (int g = 0; g < 2; g++) {
                uint32_t bh0, bh1, bh2, bh3, bl0, bl1, bl2, bl3;
                ldsm_x4(bh0, bh1, bh2, bh3, sBh + boff[g] + j * 32);
                ldsm_x4(bl0, bl1, bl2, bl3, sBl + boff[g] + j * 32);
                int n0 = g * 2, n1 = g * 2 + 1;
#pragma unroll
                for (int blk = 0; blk < 2; blk++) {
                    mma_bf16(c[blk][n0], ah[blk], bh0, bh1);
                    mma_bf16(c[blk][n1], ah[blk], bh2, bh3);
                    mma_bf16(c[blk][n0], ah[blk], bl0, bl1);
                    mma_bf16(c[blk][n1], ah[blk], bl2, bl3);
                    mma_bf16(c[blk][n0], al[blk], bh0, bh1);
                    mma_bf16(c[blk][n1], al[blk], bh2, bh3);
                }
            }
        }
        if (it + 3 < nIter) load_stage(it + 3);
        cp_commit();
    }
    cp_wait0();

    int rA = row0 + wr + (lane >> 2);
    int cA = col0 + wn + (lane & 3) * 2;
#pragma unroll
    for (int blk = 0; blk < 2; blk++) {
#pragma unroll
        for (int ni = 0; ni < 4; ni++) {
            float* p0 = C + (size_t)(rA + blk * 16) * N + cA + ni * 8;
            float* p1 = C + (size_t)(rA + blk * 16 + 8) * N + cA + ni * 8;
            *(float2*)p0 = make_float2(c[blk][ni][0], c[blk][ni][1]);
            *(float2*)p1 = make_float2(c[blk][ni][2], c[blk][ni][3]);
        }
    }
}

// ---------------- edge decode ----------------
__global__ void decode_edges_k(const int* __restrict__ ei) {
    int b = blockIdx.x;
    const int* e = ei + (size_t)b * 2 * EE;
    for (int i = threadIdx.x; i < ESL; i += blockDim.x) {
        int s, d;
        if (i < EE) { s = e[i]; d = e[EE + i]; }
        else        { s = i - EE; d = i - EE; }
        s = min(max(s, 0), NNODE - 1);
        d = min(max(d, 0), NNODE - 1);
        g_esrc[(size_t)b * ESL + i] = s;
        g_edst[(size_t)b * ESL + i] = d;
    }
}

// ---------------- CSR build ----------------
__global__ void build_csr_k() {
    int b = blockIdx.x;
    const int* es = g_esrc + (size_t)b * ESL;
    const int* ed = g_edst + (size_t)b * ESL;
    __shared__ int din[NNODE], dout[NNODE], curd[NNODE], curs[NNODE];
    int t = threadIdx.x;
    for (int i = t; i < NNODE; i += blockDim.x) { din[i] = 0; dout[i] = 0; }
    __syncthreads();
    for (int i = t; i < ESL; i += blockDim.x) {
        atomicAdd(&dout[es[i]], 1);
        atomicAdd(&din[ed[i]], 1);
    }
    __syncthreads();
    for (int n = t; n < NNODE; n += blockDim.x)
        g_dinv[b * NNODE + n] = rsqrtf(fmaxf((float)din[n], 1e-12f));
    if (t == 0) {
        int o = 0;
        for (int n = 0; n < NNODE; n++) { g_doff[b * (NNODE + 1) + n] = o; curd[n] = o; o += din[n]; }
        g_doff[b * (NNODE + 1) + NNODE] = o;
    }
    if (t == 1) {
        int o = 0;
        for (int n = 0; n < NNODE; n++) { g_soff[b * (NNODE + 1) + n] = o; curs[n] = o; o += dout[n]; }
        g_soff[b * (NNODE + 1) + NNODE] = o;
    }
    __syncthreads();
    if (t == 0)
        for (int i = 0; i < ESL; i++) g_deid[(size_t)b * ESL + curd[ed[i]]++] = i;
    if (t == 64)
        for (int i = 0; i < ESL; i++) g_seid[(size_t)b * ESL + curs[es[i]]++] = i;
}

// ---------------- GCN aggregation + bias + relu ----------------
__global__ __launch_bounds__(256) void gcn_agg_k(const float* __restrict__ b_gcn) {
    __shared__ float sH[NNODE * 64];
    int b = blockIdx.x;
    int c = blockIdx.y * 64;
    int t = threadIdx.x;
    for (int i = t; i < NNODE * 16; i += 256) {
        int n = i >> 4, j = i & 15;
        *(float4*)&sH[n * 64 + j * 4] = *(const float4*)&g_H1[(size_t)(b * NNODE + n) * HH + c + j * 4];
    }
    __syncthreads();
    int warp = t >> 5, lane = t & 31;
    float bias0 = b_gcn[c + lane * 2], bias1 = b_gcn[c + lane * 2 + 1];
    for (int n = warp; n < NNODE; n += 8) {
        float dn = g_dinv[b * NNODE + n];
        int beg = g_doff[b * (NNODE + 1) + n];
        int end = g_doff[b * (NNODE + 1) + n + 1];
        float a0 = 0.f, a1 = 0.f;
        for (int j = beg; j < end; j++) {
            int eid = g_deid[(size_t)b * ESL + j];
            int s = g_esrc[(size_t)b * ESL + eid];
            float nr = g_dinv[b * NNODE + s] * dn;
            a0 = fmaf(nr, sH[s * 64 + lane * 2], a0);
            a1 = fmaf(nr, sH[s * 64 + lane * 2 + 1], a1);
        }
        a0 = fmaxf(a0 + bias0, 0.f);
        a1 = fmaxf(a1 + bias1, 0.f);
        size_t o = (size_t)(b * NNODE + n) * HH + c + lane * 2;
        g_h[o]     = a0;
        g_h[o + 1] = a1;
    }
}

// ---------------- wa = W_gat @ a ----------------
__global__ __launch_bounds__(256) void wa_k(const float* __restrict__ W_gat,
                                            const float* __restrict__ a_src,
                                            const float* __restrict__ a_dst) {
    int warp = threadIdx.x >> 5, lane = threadIdx.x & 31;
    for (int r = warp; r < HH; r += 8) {
        const float* wr = W_gat + (size_t)r * DD;
        float s1 = 0.f, s2 = 0.f;
        for (int j = lane; j < DD; j += 32) {
            float w = wr[j];
            s1 = fmaf(w, a_src[j], s1);
            s2 = fmaf(w, a_dst[j], s2);
        }
#pragma unroll
        for (int o = 16; o > 0; o >>= 1) {
            s1 += __shfl_xor_sync(~0u, s1, o);
            s2 += __shfl_xor_sync(~0u, s2, o);
        }
        if (lane == 0) { g_wasrc[r] = s1; g_wadst[r] = s2; }
    }
}

// ---------------- asrc/adst = h @ wa ----------------
__global__ __launch_bounds__(256) void attproj_k() {
    int row = blockIdx.x * 8 + (threadIdx.x >> 5);
    int lane = threadIdx.x & 31;
    const float* h = g_h + (size_t)row * HH;
    float s1 = 0.f, s2 = 0.f;
#pragma unroll
    for (int k = lane * 4; k < HH; k += 128) {
        float4 hv = *(const float4*)(h + k);
        float4 av = *(const float4*)(g_wasrc + k);
        float4 bv = *(const float4*)(g_wadst + k);
        s1 += hv.x * av.x + hv.y * av.y + hv.z * av.z + hv.w * av.w;
        s2 += hv.x * bv.x + hv.y * bv.y + hv.z * bv.z + hv.w * bv.w;
    }
#pragma unroll
    for (int o = 16; o > 0; o >>= 1) {
        s1 += __shfl_xor_sync(~0u, s1, o);
        s2 += __shfl_xor_sync(~0u, s2, o);
    }
    if (lane == 0) { g_asrc[row] = s1; g_adst[row] = s2; }
}

// ---------------- GAT segment softmax ----------------
__global__ __launch_bounds__(256) void gat_softmax_k() {
    int b = blockIdx.x;
    int warp = threadIdx.x >> 5, lane = threadIdx.x & 31;
    for (int n = warp; n < NNODE; n += 8) {
        int beg = g_doff[b * (NNODE + 1) + n];
        int end = g_doff[b * (NNODE + 1) + n + 1];
        float adn = g_adst[b * NNODE + n];
        float m = -1e30f;
        for (int j = beg + lane; j < end; j += 32) {
            int eid = g_deid[(size_t)b * ESL + j];
            int s = g_esrc[(size_t)b * ESL + eid];
            float ev = g_asrc[b * NNODE + s] + adn;
            ev = ev >= 0.f ? ev : 0.2f * ev;
            m = fmaxf(m, ev);
        }
#pragma unroll
        for (int o = 16; o > 0; o >>= 1) m = fmaxf(m, __shfl_xor_sync(~0u, m, o));
        float sum = 0.f;
        for (int j = beg + lane; j < end; j += 32) {
            int eid = g_deid[(size_t)b * ESL + j];
            int s = g_esrc[(size_t)b * ESL + eid];
            float ev = g_asrc[b * NNODE + s] + adn;
            ev = ev >= 0.f ? ev : 0.2f * ev;
            sum += expf(ev - m);
        }
#pragma unroll
        for (int o = 16; o > 0; o >>= 1) sum += __shfl_xor_sync(~0u, sum, o);
        float inv = 1.f / sum;
        for (int j = beg + lane; j < end; j += 32) {
            int eid = g_deid[(size_t)b * ESL + j];
            int s = g_esrc[(size_t)b * ESL + eid];
            float ev = g_asrc[b * NNODE + s] + adn;
            ev = ev >= 0.f ? ev : 0.2f * ev;
            g_alpha[(size_t)b * ESL + eid] = expf(ev - m) * inv;
        }
    }
}

// ---------------- patch attention scores ----------------
__global__ __launch_bounds__(256) void scores_k() {
    int b = blockIdx.x;
    int warp = threadIdx.x >> 5, lane = threadIdx.x & 31;
    for (int n = warp; n < NNODE; n += 8) {
        int db = g_doff[b * (NNODE + 1) + n], de = g_doff[b * (NNODE + 1) + n + 1];
        int sb = g_soff[b * (NNODE + 1) + n], se = g_soff[b * (NNODE + 1) + n + 1];
        float s = 0.f;
        for (int j = db + lane; j < de; j += 32) s += g_alpha[(size_t)b * ESL + g_deid[(size_t)b * ESL + j]];
        for (int j = sb + lane; j < se; j += 32) s += g_alpha[(size_t)b * ESL + g_seid[(size_t)b * ESL + j]];
#pragma unroll
        for (int o = 16; o > 0; o >>= 1) s += __shfl_xor_sync(~0u, s, o);
        if (lane == 0)
            g_scores[b * NNODE + n] = s / (float)((de - db) + (se - sb));
    }
}

// ---------------- top-k (SMEM scratch) ----------------
__global__ __launch_bounds__(1024) void topk_k() {
    extern __shared__ float sc[];
    int t = threadIdx.x;
    for (int i = t; i < BN; i += 1024) sc[i] = g_scores[i];
    __syncthreads();
    __shared__ float bv[1024];
    __shared__ int   bi[1024];
    for (int it = 0; it < KTOP; it++) {
        float best = -1e30f; int besti = 0x7fffffff;
        for (int i = t; i < BN; i += 1024) {
            float v = sc[i];
            if (v > best || (v == best && i < besti)) { best = v; besti = i; }
        }
        bv[t] = best; bi[t] = besti;
        __syncthreads();
        for (int s = 512; s > 0; s >>= 1) {
            if (t < s) {
                float v = bv[t + s]; int i2 = bi[t + s];
                if (v > bv[t] || (v == bv[t] && i2 < bi[t])) { bv[t] = v; bi[t] = i2; }
            }
            __syncthreads();
        }
        if (t == 0) { g_topk[it] = bi[0]; sc[bi[0]] = -1e30f; }
        __syncthreads();
    }
}

// ---------------- final: aggregate(512) -> @W_gat -> +b_gat -> @W_proj ----------------
__global__ __launch_bounds__(256) void final_k(
    const float* __restrict__ W_gat, const float* __restrict__ b_gat,
    const float* __restrict__ W_proj, const float* __restrict__ b_proj,
    float* __restrict__ out)
{
    __shared__ float agg[HH];
    __shared__ float gfe[DD];
    int node = g_topk[blockIdx.x];
    int b = node / NNODE, n = node % NNODE;
    int t = threadIdx.x;

    int beg = g_doff[b * (NNODE + 1) + n];
    int end = g_doff[b * (NNODE + 1) + n + 1];
#pragma unroll
    for (int half = 0; half < 2; half++) {
        int k = t + half * 256;
        float acc = 0.f;
        for (int j = beg; j < end; j++) {
            int eid = g_deid[(size_t)b * ESL + j];
            int s = g_esrc[(size_t)b * ESL + eid];
            acc = fmaf(g_alpha[(size_t)b * ESL + eid],
                       g_h[(size_t)(b * NNODE + s) * HH + k], acc);
        }
        agg[k] = acc;
    }
    __syncthreads();

    {
        float acc = b_gat[t];
#pragma unroll 4
        for (int k = 0; k < HH; k++)
            acc = fmaf(agg[k], W_gat[(size_t)k * DD + t], acc);
        gfe[t] = acc;
    }
    __syncthreads();

    int p = t * 4;
    float4 o = *(const float4*)&b_proj[p];
#pragma unroll 4
    for (int k = 0; k < DD; k++) {
        float gv = gfe[k];
        const float4 w = *(const float4*)&W_proj[(size_t)k * PP + p];
        o.x = fmaf(gv, w.x, o.x);
        o.y = fmaf(gv, w.y, o.y);
        o.z = fmaf(gv, w.z, o.z);
        o.w = fmaf(gv, w.w, o.w);
    }
    *(float4*)&out[(size_t)blockIdx.x * PP + p] = o;
}

// ---------------- launch ----------------
extern "C" void kernel_launch(void* const* d_in, const int* in_sizes, int n_in,
                              void* d_out, int out_size)
{
    const float* x      = (const float*)d_in[0];
    const int*   ei     = (const int*)d_in[1];
    const float* W_gcn  = (const float*)d_in[2];
    const float* b_gcn  = (const float*)d_in[3];
    const float* W_gat  = (const float*)d_in[4];
    const float* b_gat  = (const float*)d_in[5];
    const float* a_src  = (const float*)d_in[6];
    const float* a_dst  = (const float*)d_in[7];
    const float* W_proj = (const float*)d_in[8];
    const float* b_proj = (const float*)d_in[9];

    __nv_bfloat16 *pW1hi, *pW1lo;
    float *pH1;
    cudaGetSymbolAddress((void**)&pW1hi, g_W1hi);
    cudaGetSymbolAddress((void**)&pW1lo, g_W1lo);
    cudaGetSymbolAddress((void**)&pH1,   g_H1);

    cudaFuncSetAttribute(mma_gemm, cudaFuncAttributeMaxDynamicSharedMemorySize, NSTAGE * STAGE_B);
    cudaFuncSetAttribute(topk_k,   cudaFuncAttributeMaxDynamicSharedMemorySize, BN * sizeof(float));

    // indices 0..2: prep; index 3 = mma_gemm (ncu capture slot)
    splitT_k<<<dim3(FF / 32, HH / 32), dim3(32, 8)>>>(W_gcn, pW1hi, pW1lo, FF, HH);
    decode_edges_k<<<BB, 256>>>(ei);
    build_csr_k<<<BB, 128>>>();

    mma_gemm<<<dim3(HH / 128, BN / 128), 512, NSTAGE * STAGE_B>>>(
        x, pW1hi, pW1lo, pH1, BN, HH, FF);

    gcn_agg_k<<<dim3(BB, HH / 64), 256>>>(b_gcn);
    wa_k<<<1, 256>>>(W_gat, a_src, a_dst);
    attproj_k<<<BN / 8, 256>>>();
    gat_softmax_k<<<BB, 256>>>();
    scores_k<<<BB, 256>>>();
    topk_k<<<1, 1024, BN * sizeof(float)>>>();
    final_k<<<KTOP, 256>>>(W_gat, b_gat, W_proj, b_proj, (float*)d_out);
}

// round 8
// speedup vs baseline: 1.0873x; 1.0873x over previous
#include <cuda_runtime.h>
#include <cuda_bf16.h>
#include <math.h>
#include <stdint.h>

#define BB    256
#define NNODE 100
#define EE    1600
#define ESL   1700
#define FF    2048
#define HH    512
#define DD    256
#define PP    1024
#define KTOP  50
#define BN    (BB*NNODE)   // 25600

// ---------------- scratch ----------------
__device__ __align__(16) __nv_bfloat16 g_W1hi[(size_t)HH*FF];
__device__ __align__(16) __nv_bfloat16 g_W1lo[(size_t)HH*FF];
__device__ __align__(16) float g_H1[(size_t)BN*HH];
__device__ __align__(16) float g_h [(size_t)BN*HH];
__device__ float g_wasrc[HH];
__device__ float g_wadst[HH];
__device__ float g_dinv[BN];
__device__ float g_asrc[BN];
__device__ float g_adst[BN];
__device__ float g_alpha[(size_t)BB*ESL];
__device__ int   g_esrc[(size_t)BB*ESL];
__device__ int   g_edst[(size_t)BB*ESL];
__device__ int   g_doff[BB*(NNODE+1)];
__device__ int   g_soff[BB*(NNODE+1)];
__device__ int   g_deid[(size_t)BB*ESL];
__device__ int   g_seid[(size_t)BB*ESL];
__device__ float g_scores[BN];
__device__ int   g_topk[KTOP];

// ---------------- helpers ----------------
__device__ __forceinline__ uint32_t smem_u32(const void* p) {
    uint32_t a;
    asm("{ .reg .u64 t; cvta.to.shared.u64 t, %1; cvt.u32.u64 %0, t; }" : "=r"(a) : "l"(p));
    return a;
}
__device__ __forceinline__ void cp_async16(uint32_t dst, const void* src) {
    asm volatile("cp.async.cg.shared.global [%0], [%1], 16;" :: "r"(dst), "l"(src) : "memory");
}
__device__ __forceinline__ void cp_commit() {
    asm volatile("cp.async.commit_group;" ::: "memory");
}
__device__ __forceinline__ void cp_wait0() {
    asm volatile("cp.async.wait_group 0;" ::: "memory");
}
__device__ __forceinline__ void cp_wait1() {
    asm volatile("cp.async.wait_group 1;" ::: "memory");
}
__device__ __forceinline__ void ldsm_x4(uint32_t& r0, uint32_t& r1, uint32_t& r2, uint32_t& r3, uint32_t a) {
    asm volatile("ldmatrix.sync.aligned.m8n8.x4.shared.b16 {%0,%1,%2,%3}, [%4];"
                 : "=r"(r0), "=r"(r1), "=r"(r2), "=r"(r3) : "r"(a));
}
__device__ __forceinline__ void mma_bf16(float* c, const uint32_t* a, uint32_t b0, uint32_t b1) {
    asm volatile(
        "mma.sync.aligned.m16n8k16.row.col.f32.bf16.bf16.f32 "
        "{%0,%1,%2,%3}, {%4,%5,%6,%7}, {%8,%9}, {%0,%1,%2,%3};"
        : "+f"(c[0]), "+f"(c[1]), "+f"(c[2]), "+f"(c[3])
        : "r"(a[0]), "r"(a[1]), "r"(a[2]), "r"(a[3]), "r"(b0), "r"(b1));
}
__device__ __forceinline__ void split2(float v, __nv_bfloat16& h, __nv_bfloat16& l) {
    h = __float2bfloat16_rn(v);
    l = __float2bfloat16_rn(v - __bfloat162float(h));
}
__device__ __forceinline__ void splitpair(float x0, float x1, uint32_t& hi, uint32_t& lo) {
    asm("cvt.rn.bf16x2.f32 %0, %1, %2;" : "=r"(hi) : "f"(x1), "f"(x0));
    __nv_bfloat162 b = *reinterpret_cast<__nv_bfloat162*>(&hi);
    float h0 = __bfloat162float(b.x), h1 = __bfloat162float(b.y);
    asm("cvt.rn.bf16x2.f32 %0, %1, %2;" : "=r"(lo) : "f"(x1 - h1), "f"(x0 - h0));
}

// ---------------- weight transpose + split ----------------
__global__ void splitT_k(const float* __restrict__ W, __nv_bfloat16* __restrict__ Thi,
                         __nv_bfloat16* __restrict__ Tlo, int R, int C) {
    __shared__ float tile[32][33];
    int rb = blockIdx.x * 32, cb = blockIdx.y * 32;
    int tx = threadIdx.x, ty = threadIdx.y;
#pragma unroll
    for (int i = 0; i < 4; i++)
        tile[ty + i * 8][tx] = W[(size_t)(rb + ty + i * 8) * C + cb + tx];
    __syncthreads();
#pragma unroll
    for (int i = 0; i < 4; i++) {
        float v = tile[tx][ty + i * 8];
        __nv_bfloat16 h, l; split2(v, h, l);
        size_t o = (size_t)(cb + ty + i * 8) * R + rb + tx;
        Thi[o] = h; Tlo[o] = l;
    }
}

// ---------------- fused-split mma.sync GEMM: 512 thr, 2 CTAs/SM ----------------
#define ARS      160
#define BRS      80
#define A_TILE   (128*ARS)              // 20480
#define B_TILE   (128*BRS)              // 10240
#define STAGE_B  (A_TILE + 2*B_TILE)    // 40960
#define NSTAGE   2
__global__ __launch_bounds__(512, 2) void mma_gemm(
    const float* __restrict__ A,
    const __nv_bfloat16* __restrict__ Bhi, const __nv_bfloat16* __restrict__ Blo,
    float* __restrict__ C, int M, int N, int K)
{
    extern __shared__ __align__(16) char smem[];
    uint32_t sb = smem_u32(smem);
    int t = threadIdx.x;
    int lane = t & 31, w = t >> 5;
    int row0 = blockIdx.y * 128, col0 = blockIdx.x * 128;
    int wr = (w & 3) * 32, wn = (w >> 2) * 32;

    uint32_t aso[2]; int aqr[2], aqc[2];
#pragma unroll
    for (int i = 0; i < 2; i++) {
        int q = t + 512 * i;
        aqr[i] = q >> 3; aqc[i] = q & 7;
        aso[i] = (uint32_t)(aqr[i] * ARS + aqc[i] * 16);
    }
    int bqr = t >> 2, bqc = t & 3;
    uint32_t bso = (uint32_t)(bqr * BRS + bqc * 16);

    uint32_t a_base[2];
#pragma unroll
    for (int blk = 0; blk < 2; blk++)
        a_base[blk] = (uint32_t)((wr + blk * 16 + (lane >> 2)) * ARS + (lane & 3) * 8);

    uint32_t boff[2];
#pragma unroll
    for (int g = 0; g < 2; g++) {
        int quad = lane >> 3;
        int rB = wn + g * 16 + (lane & 7) + (quad >> 1) * 8;
        boff[g] = (uint32_t)(rB * BRS + (quad & 1) * 16);
    }

    float c[2][4][4];
#pragma unroll
    for (int i = 0; i < 2; i++)
#pragma unroll
        for (int jn = 0; jn < 4; jn++)
#pragma unroll
            for (int e = 0; e < 4; e++) c[i][jn][e] = 0.f;

    int nIter = K >> 5;

    auto load_stage = [&](int s) {
        uint32_t st = sb + (s & 1) * STAGE_B;
        int k0 = s << 5;
#pragma unroll
        for (int i = 0; i < 2; i++)
            cp_async16(st + aso[i], A + (size_t)(row0 + aqr[i]) * K + k0 + aqc[i] * 4);
        cp_async16(st + A_TILE + bso,          Bhi + (size_t)(col0 + bqr) * K + k0 + bqc * 8);
        cp_async16(st + A_TILE + B_TILE + bso, Blo + (size_t)(col0 + bqr) * K + k0 + bqc * 8);
    };

    load_stage(0); cp_commit();

    for (int it = 0; it < nIter; it++) {
        if (it + 1 < nIter) { load_stage(it + 1); cp_commit(); cp_wait1(); }
        else                { cp_wait0(); }
        __syncthreads();

        uint32_t st = sb + (it & 1) * STAGE_B;
        uint32_t sA = st, sBh = st + A_TILE, sBl = st + B_TILE + A_TILE;

#pragma unroll
        for (int j = 0; j < 2; j++) {
            uint32_t ah[2][4], al[2][4];
#pragma unroll
            for (int blk = 0; blk < 2; blk++) {
                uint32_t base = sA + a_base[blk] + j * 64;
#pragma unroll
                for (int part = 0; part < 2; part++) {
#pragma unroll
                    for (int rr = 0; rr < 2; rr++) {
                        float2 v;
                        asm volatile("ld.shared.v2.f32 {%0,%1}, [%2];"
                                     : "=f"(v.x), "=f"(v.y)
                                     : "r"(base + part * 32 + rr * (8 * ARS)));
                        int idx = part * 2 + rr;
                        splitpair(v.x, v.y, ah[blk][idx], al[blk][idx]);
                    }
                }
            }
#pragma unroll
            for (int g = 0; g < 2; g++) {
                uint32_t bh0, bh1, bh2, bh3, bl0, bl1, bl2, bl3;
                ldsm_x4(bh0, bh1, bh2, bh3, sBh + boff[g] + j * 32);
                ldsm_x4(bl0, bl1, bl2, bl3, sBl + boff[g] + j * 32);
                int n0 = g * 2, n1 = g * 2 + 1;
#pragma unroll
                for (int blk = 0; blk < 2; blk++) {
                    mma_bf16(c[blk][n0], ah[blk], bh0, bh1);
                    mma_bf16(c[blk][n1], ah[blk], bh2, bh3);
                    mma_bf16(c[blk][n0], ah[blk], bl0, bl1);
                    mma_bf16(c[blk][n1], ah[blk], bl2, bl3);
                    mma_bf16(c[blk][n0], al[blk], bh0, bh1);
                    mma_bf16(c[blk][n1], al[blk], bh2, bh3);
                }
            }
        }
        __syncthreads();   // protect buffer reuse (WAR vs next load_stage)
    }

    int rA = row0 + wr + (lane >> 2);
    int cA = col0 + wn + (lane & 3) * 2;
#pragma unroll
    for (int blk = 0; blk < 2; blk++) {
#pragma unroll
        for (int ni = 0; ni < 4; ni++) {
            float* p0 = C + (size_t)(rA + blk * 16) * N + cA + ni * 8;
            float* p1 = C + (size_t)(rA + blk * 16 + 8) * N + cA + ni * 8;
            *(float2*)p0 = make_float2(c[blk][ni][0], c[blk][ni][1]);
            *(float2*)p1 = make_float2(c[blk][ni][2], c[blk][ni][3]);
        }
    }
}

// ---------------- edge decode ----------------
__global__ void decode_edges_k(const int* __restrict__ ei) {
    int b = blockIdx.x;
    const int* e = ei + (size_t)b * 2 * EE;
    for (int i = threadIdx.x; i < ESL; i += blockDim.x) {
        int s, d;
        if (i < EE) { s = e[i]; d = e[EE + i]; }
        else        { s = i - EE; d = i - EE; }
        s = min(max(s, 0), NNODE - 1);
        d = min(max(d, 0), NNODE - 1);
        g_esrc[(size_t)b * ESL + i] = s;
        g_edst[(size_t)b * ESL + i] = d;
    }
}

// ---------------- CSR build (parallel stable fill) ----------------
__global__ __launch_bounds__(256) void build_csr_k() {
    int b = blockIdx.x;
    __shared__ int sed[ESL], ses[ESL];
    __shared__ int din[NNODE], dout[NNODE];
    __shared__ int doffS[NNODE + 1], soffS[NNODE + 1];
    int t = threadIdx.x;
    for (int i = t; i < NNODE; i += 256) { din[i] = 0; dout[i] = 0; }
    __syncthreads();
    for (int i = t; i < ESL; i += 256) {
        int s = g_esrc[(size_t)b * ESL + i];
        int d = g_edst[(size_t)b * ESL + i];
        ses[i] = s; sed[i] = d;
        atomicAdd(&dout[s], 1);
        atomicAdd(&din[d], 1);
    }
    __syncthreads();
    for (int n = t; n < NNODE; n += 256)
        g_dinv[b * NNODE + n] = rsqrtf(fmaxf((float)din[n], 1e-12f));
    if (t == 0) {
        int o = 0;
        for (int n = 0; n < NNODE; n++) { doffS[n] = o; o += din[n]; }
        doffS[NNODE] = o;
    }
    if (t == 32) {
        int o = 0;
        for (int n = 0; n < NNODE; n++) { soffS[n] = o; o += dout[n]; }
        soffS[NNODE] = o;
    }
    __syncthreads();
    for (int n = t; n <= NNODE; n += 256) {
        g_doff[b * (NNODE + 1) + n] = doffS[n];
        g_soff[b * (NNODE + 1) + n] = soffS[n];
    }
    // parallel stable fill: one thread per node scans all edges in order
    if (t < NNODE) {
        int n = t, pos = doffS[n];
        for (int i = 0; i < ESL; i++)
            if (sed[i] == n) g_deid[(size_t)b * ESL + pos++] = i;
    } else if (t >= 128 && t < 128 + NNODE) {
        int n = t - 128, pos = soffS[n];
        for (int i = 0; i < ESL; i++)
            if (ses[i] == n) g_seid[(size_t)b * ESL + pos++] = i;
    }
}

// ---------------- GCN aggregation (all-SMEM) + bias + relu ----------------
__global__ __launch_bounds__(256) void gcn_agg_k(const float* __restrict__ b_gcn) {
    __shared__ float sH[NNODE * 64];
    __shared__ float sW[ESL];      // dinv[src] per dst-sorted position
    __shared__ int   sSrc[ESL];    // src id per dst-sorted position
    __shared__ float sDinv[NNODE];
    int b = blockIdx.x;
    int c = blockIdx.y * 64;
    int t = threadIdx.x;
    for (int i = t; i < NNODE; i += 256) sDinv[i] = g_dinv[b * NNODE + i];
    for (int i = t; i < ESL; i += 256) {
        int eid = g_deid[(size_t)b * ESL + i];
        int s = g_esrc[(size_t)b * ESL + eid];
        sSrc[i] = s;
        sW[i] = g_dinv[b * NNODE + s];
    }
    for (int i = t; i < NNODE * 16; i += 256) {
        int n = i >> 4, j = i & 15;
        *(float4*)&sH[n * 64 + j * 4] = *(const float4*)&g_H1[(size_t)(b * NNODE + n) * HH + c + j * 4];
    }
    __syncthreads();
    int warp = t >> 5, lane = t & 31;
    float bias0 = b_gcn[c + lane * 2], bias1 = b_gcn[c + lane * 2 + 1];
    for (int n = warp; n < NNODE; n += 8) {
        float dn = sDinv[n];
        int beg = g_doff[b * (NNODE + 1) + n];
        int end = g_doff[b * (NNODE + 1) + n + 1];
        float a0 = 0.f, a1 = 0.f;
        for (int j = beg; j < end; j++) {
            int s = sSrc[j];
            float nr = sW[j] * dn;
            a0 = fmaf(nr, sH[s * 64 + lane * 2], a0);
            a1 = fmaf(nr, sH[s * 64 + lane * 2 + 1], a1);
        }
        a0 = fmaxf(a0 + bias0, 0.f);
        a1 = fmaxf(a1 + bias1, 0.f);
        size_t o = (size_t)(b * NNODE + n) * HH + c + lane * 2;
        g_h[o]     = a0;
        g_h[o + 1] = a1;
    }
}

// ---------------- wa = W_gat @ a ----------------
__global__ __launch_bounds__(256) void wa_k(const float* __restrict__ W_gat,
                                            const float* __restrict__ a_src,
                                            const float* __restrict__ a_dst) {
    int warp = threadIdx.x >> 5, lane = threadIdx.x & 31;
    for (int r = warp; r < HH; r += 8) {
        const float* wr = W_gat + (size_t)r * DD;
        float s1 = 0.f, s2 = 0.f;
        for (int j = lane; j < DD; j += 32) {
            float w = wr[j];
            s1 = fmaf(w, a_src[j], s1);
            s2 = fmaf(w, a_dst[j], s2);
        }
#pragma unroll
        for (int o = 16; o > 0; o >>= 1) {
            s1 += __shfl_xor_sync(~0u, s1, o);
            s2 += __shfl_xor_sync(~0u, s2, o);
        }
        if (lane == 0) { g_wasrc[r] = s1; g_wadst[r] = s2; }
    }
}

// ---------------- asrc/adst = h @ wa ----------------
__global__ __launch_bounds__(256) void attproj_k() {
    int row = blockIdx.x * 8 + (threadIdx.x >> 5);
    int lane = threadIdx.x & 31;
    const float* h = g_h + (size_t)row * HH;
    float s1 = 0.f, s2 = 0.f;
#pragma unroll
    for (int k = lane * 4; k < HH; k += 128) {
        float4 hv = *(const float4*)(h + k);
        float4 av = *(const float4*)(g_wasrc + k);
        float4 bv = *(const float4*)(g_wadst + k);
        s1 += hv.x * av.x + hv.y * av.y + hv.z * av.z + hv.w * av.w;
        s2 += hv.x * bv.x + hv.y * bv.y + hv.z * bv.z + hv.w * bv.w;
    }
#pragma unroll
    for (int o = 16; o > 0; o >>= 1) {
        s1 += __shfl_xor_sync(~0u, s1, o);
        s2 += __shfl_xor_sync(~0u, s2, o);
    }
    if (lane == 0) { g_asrc[row] = s1; g_adst[row] = s2; }
}

// ---------------- GAT segment softmax (SMEM-staged) ----------------
__global__ __launch_bounds__(256) void gat_softmax_k() {
    __shared__ float sEv[ESL];   // asrc[src] per dst-sorted position
    __shared__ int   sEid[ESL];  // edge id per dst-sorted position
    int b = blockIdx.x;
    int t = threadIdx.x;
    for (int i = t; i < ESL; i += 256) {
        int eid = g_deid[(size_t)b * ESL + i];
        int s = g_esrc[(size_t)b * ESL + eid];
        sEid[i] = eid;
        sEv[i] = g_asrc[b * NNODE + s];
    }
    __syncthreads();
    int warp = t >> 5, lane = t & 31;
    for (int n = warp; n < NNODE; n += 8) {
        int beg = g_doff[b * (NNODE + 1) + n];
        int end = g_doff[b * (NNODE + 1) + n + 1];
        float adn = g_adst[b * NNODE + n];
        float m = -1e30f;
        for (int j = beg + lane; j < end; j += 32) {
            float ev = sEv[j] + adn;
            ev = ev >= 0.f ? ev : 0.2f * ev;
            m = fmaxf(m, ev);
        }
#pragma unroll
        for (int o = 16; o > 0; o >>= 1) m = fmaxf(m, __shfl_xor_sync(~0u, m, o));
        float sum = 0.f;
        for (int j = beg + lane; j < end; j += 32) {
            float ev = sEv[j] + adn;
            ev = ev >= 0.f ? ev : 0.2f * ev;
            sum += expf(ev - m);
        }
#pragma unroll
        for (int o = 16; o > 0; o >>= 1) sum += __shfl_xor_sync(~0u, sum, o);
        float inv = 1.f / sum;
        for (int j = beg + lane; j < end; j += 32) {
            float ev = sEv[j] + adn;
            ev = ev >= 0.f ? ev : 0.2f * ev;
            g_alpha[(size_t)b * ESL + sEid[j]] = expf(ev - m) * inv;
        }
    }
}

// ---------------- patch attention scores (SMEM-staged) ----------------
__global__ __launch_bounds__(256) void scores_k() {
    __shared__ float sAl[ESL];
    __shared__ int   sDe[ESL], sSe[ESL];
    int b = blockIdx.x;
    int t = threadIdx.x;
    for (int i = t; i < ESL; i += 256) {
        sAl[i] = g_alpha[(size_t)b * ESL + i];
        sDe[i] = g_deid[(size_t)b * ESL + i];
        sSe[i] = g_seid[(size_t)b * ESL + i];
    }
    __syncthreads();
    int warp = t >> 5, lane = t & 31;
    for (int n = warp; n < NNODE; n += 8) {
        int db = g_doff[b * (NNODE + 1) + n], de = g_doff[b * (NNODE + 1) + n + 1];
        int sb = g_soff[b * (NNODE + 1) + n], se = g_soff[b * (NNODE + 1) + n + 1];
        float s = 0.f;
        for (int j = db + lane; j < de; j += 32) s += sAl[sDe[j]];
        for (int j = sb + lane; j < se; j += 32) s += sAl[sSe[j]];
#pragma unroll
        for (int o = 16; o > 0; o >>= 1) s += __shfl_xor_sync(~0u, s, o);
        if (lane == 0)
            g_scores[b * NNODE + n] = s / (float)((de - db) + (se - sb));
    }
}

// ---------------- top-k ----------------
__global__ __launch_bounds__(1024) void topk_k() {
    extern __shared__ float sc[];
    int t = threadIdx.x;
    for (int i = t; i < BN; i += 1024) sc[i] = g_scores[i];
    __syncthreads();
    __shared__ float bv[1024];
    __shared__ int   bi[1024];
    for (int it = 0; it < KTOP; it++) {
        float best = -1e30f; int besti = 0x7fffffff;
        for (int i = t; i < BN; i += 1024) {
            float v = sc[i];
            if (v > best || (v == best && i < besti)) { best = v; besti = i; }
        }
        bv[t] = best; bi[t] = besti;
        __syncthreads();
        for (int s = 512; s > 0; s >>= 1) {
            if (t < s) {
                float v = bv[t + s]; int i2 = bi[t + s];
                if (v > bv[t] || (v == bv[t] && i2 < bi[t])) { bv[t] = v; bi[t] = i2; }
            }
            __syncthreads();
        }
        if (t == 0) { g_topk[it] = bi[0]; sc[bi[0]] = -1e30f; }
        __syncthreads();
    }
}

// ---------------- final: aggregate(512) -> @W_gat -> +b_gat -> @W_proj ----------------
__global__ __launch_bounds__(256) void final_k(
    const float* __restrict__ W_gat, const float* __restrict__ b_gat,
    const float* __restrict__ W_proj, const float* __restrict__ b_proj,
    float* __restrict__ out)
{
    __shared__ float agg[HH];
    __shared__ float gfe[DD];
    int node = g_topk[blockIdx.x];
    int b = node / NNODE, n = node % NNODE;
    int t = threadIdx.x;

    int beg = g_doff[b * (NNODE + 1) + n];
    int end = g_doff[b * (NNODE + 1) + n + 1];
#pragma unroll
    for (int half = 0; half < 2; half++) {
        int k = t + half * 256;
        float acc = 0.f;
        for (int j = beg; j < end; j++) {
            int eid = g_deid[(size_t)b * ESL + j];
            int s = g_esrc[(size_t)b * ESL + eid];
            acc = fmaf(g_alpha[(size_t)b * ESL + eid],
                       g_h[(size_t)(b * NNODE + s) * HH + k], acc);
        }
        agg[k] = acc;
    }
    __syncthreads();

    {
        float acc = b_gat[t];
#pragma unroll 4
        for (int k = 0; k < HH; k++)
            acc = fmaf(agg[k], W_gat[(size_t)k * DD + t], acc);
        gfe[t] = acc;
    }
    __syncthreads();

    int p = t * 4;
    float4 o = *(const float4*)&b_proj[p];
#pragma unroll 4
    for (int k = 0; k < DD; k++) {
        float gv = gfe[k];
        const float4 w = *(const float4*)&W_proj[(size_t)k * PP + p];
        o.x = fmaf(gv, w.x, o.x);
        o.y = fmaf(gv, w.y, o.y);
        o.z = fmaf(gv, w.z, o.z);
        o.w = fmaf(gv, w.w, o.w);
    }
    *(float4*)&out[(size_t)blockIdx.x * PP + p] = o;
}

// ---------------- launch ----------------
extern "C" void kernel_launch(void* const* d_in, const int* in_sizes, int n_in,
                              void* d_out, int out_size)
{
    const float* x      = (const float*)d_in[0];
    const int*   ei     = (const int*)d_in[1];
    const float* W_gcn  = (const float*)d_in[2];
    const float* b_gcn  = (const float*)d_in[3];
    const float* W_gat  = (const float*)d_in[4];
    const float* b_gat  = (const float*)d_in[5];
    const float* a_src  = (const float*)d_in[6];
    const float* a_dst  = (const float*)d_in[7];
    const float* W_proj = (const float*)d_in[8];
    const float* b_proj = (const float*)d_in[9];

    __nv_bfloat16 *pW1hi, *pW1lo;
    float *pH1;
    cudaGetSymbolAddress((void**)&pW1hi, g_W1hi);
    cudaGetSymbolAddress((void**)&pW1lo, g_W1lo);
    cudaGetSymbolAddress((void**)&pH1,   g_H1);

    cudaFuncSetAttribute(mma_gemm, cudaFuncAttributeMaxDynamicSharedMemorySize, NSTAGE * STAGE_B);
    cudaFuncSetAttribute(topk_k,   cudaFuncAttributeMaxDynamicSharedMemorySize, BN * sizeof(float));

    // indices 0..2: prep; index 3 = mma_gemm (ncu capture slot)
    splitT_k<<<dim3(FF / 32, HH / 32), dim3(32, 8)>>>(W_gcn, pW1hi, pW1lo, FF, HH);
    decode_edges_k<<<BB, 256>>>(ei);
    build_csr_k<<<BB, 256>>>();

    mma_gemm<<<dim3(HH / 128, BN / 128), 512, NSTAGE * STAGE_B>>>(
        x, pW1hi, pW1lo, pH1, BN, HH, FF);

    gcn_agg_k<<<dim3(BB, HH / 64), 256>>>(b_gcn);
    wa_k<<<1, 256>>>(W_gat, a_src, a_dst);
    attproj_k<<<BN / 8, 256>>>();
    gat_softmax_k<<<BB, 256>>>();
    scores_k<<<BB, 256>>>();
    topk_k<<<1, 1024, BN * sizeof(float)>>>();
    final_k<<<KTOP, 256>>>(W_gat, b_gat, W_proj, b_proj, (float*)d_out);
}

// round 9
// speedup vs baseline: 1.0938x; 1.0060x over previous
#include <cuda_runtime.h>
#include <cuda_bf16.h>
#include <math.h>
#include <stdint.h>

#define BB    256
#define NNODE 100
#define EE    1600
#define ESL   1700
#define FF    2048
#define HH    512
#define DD    256
#define PP    1024
#define KTOP  50
#define BN    (BB*NNODE)   // 25600

// ---------------- scratch ----------------
__device__ __align__(16) __nv_bfloat16 g_W1hi[(size_t)HH*FF];
__device__ __align__(16) __nv_bfloat16 g_W1lo[(size_t)HH*FF];
__device__ __align__(16) float g_H1[(size_t)BN*HH];
__device__ __align__(16) float g_h [(size_t)BN*HH];
__device__ float g_wasrc[HH];
__device__ float g_wadst[HH];
__device__ float g_dinv[BN];
__device__ float g_asrc[BN];
__device__ float g_adst[BN];
__device__ float g_aspart[8*BN];
__device__ float g_adpart[8*BN];
__device__ float g_alpha[(size_t)BB*ESL];
__device__ int   g_esrc[(size_t)BB*ESL];
__device__ int   g_edst[(size_t)BB*ESL];
__device__ int   g_doff[BB*(NNODE+1)];
__device__ int   g_soff[BB*(NNODE+1)];
__device__ int   g_deid[(size_t)BB*ESL];
__device__ int   g_seid[(size_t)BB*ESL];
__device__ float g_scores[BN];
__device__ int   g_topk[KTOP];

// ---------------- helpers ----------------
__device__ __forceinline__ uint32_t smem_u32(const void* p) {
    uint32_t a;
    asm("{ .reg .u64 t; cvta.to.shared.u64 t, %1; cvt.u32.u64 %0, t; }" : "=r"(a) : "l"(p));
    return a;
}
__device__ __forceinline__ void cp_async16(uint32_t dst, const void* src) {
    asm volatile("cp.async.cg.shared.global [%0], [%1], 16;" :: "r"(dst), "l"(src) : "memory");
}
__device__ __forceinline__ void cp_commit() {
    asm volatile("cp.async.commit_group;" ::: "memory");
}
__device__ __forceinline__ void cp_wait0() {
    asm volatile("cp.async.wait_group 0;" ::: "memory");
}
__device__ __forceinline__ void cp_wait1() {
    asm volatile("cp.async.wait_group 1;" ::: "memory");
}
__device__ __forceinline__ void ldsm_x4(uint32_t& r0, uint32_t& r1, uint32_t& r2, uint32_t& r3, uint32_t a) {
    asm volatile("ldmatrix.sync.aligned.m8n8.x4.shared.b16 {%0,%1,%2,%3}, [%4];"
                 : "=r"(r0), "=r"(r1), "=r"(r2), "=r"(r3) : "r"(a));
}
__device__ __forceinline__ void mma_bf16(float* c, const uint32_t* a, uint32_t b0, uint32_t b1) {
    asm volatile(
        "mma.sync.aligned.m16n8k16.row.col.f32.bf16.bf16.f32 "
        "{%0,%1,%2,%3}, {%4,%5,%6,%7}, {%8,%9}, {%0,%1,%2,%3};"
        : "+f"(c[0]), "+f"(c[1]), "+f"(c[2]), "+f"(c[3])
        : "r"(a[0]), "r"(a[1]), "r"(a[2]), "r"(a[3]), "r"(b0), "r"(b1));
}
__device__ __forceinline__ void split2(float v, __nv_bfloat16& h, __nv_bfloat16& l) {
    h = __float2bfloat16_rn(v);
    l = __float2bfloat16_rn(v - __bfloat162float(h));
}
__device__ __forceinline__ void splitpair(float x0, float x1, uint32_t& hi, uint32_t& lo) {
    asm("cvt.rn.bf16x2.f32 %0, %1, %2;" : "=r"(hi) : "f"(x1), "f"(x0));
    __nv_bfloat162 b = *reinterpret_cast<__nv_bfloat162*>(&hi);
    float h0 = __bfloat162float(b.x), h1 = __bfloat162float(b.y);
    asm("cvt.rn.bf16x2.f32 %0, %1, %2;" : "=r"(lo) : "f"(x1 - h1), "f"(x0 - h0));
}

// ---------------- weight transpose + split ----------------
__global__ void splitT_k(const float* __restrict__ W, __nv_bfloat16* __restrict__ Thi,
                         __nv_bfloat16* __restrict__ Tlo, int R, int C) {
    __shared__ float tile[32][33];
    int rb = blockIdx.x * 32, cb = blockIdx.y * 32;
    int tx = threadIdx.x, ty = threadIdx.y;
#pragma unroll
    for (int i = 0; i < 4; i++)
        tile[ty + i * 8][tx] = W[(size_t)(rb + ty + i * 8) * C + cb + tx];
    __syncthreads();
#pragma unroll
    for (int i = 0; i < 4; i++) {
        float v = tile[tx][ty + i * 8];
        __nv_bfloat16 h, l; split2(v, h, l);
        size_t o = (size_t)(cb + ty + i * 8) * R + rb + tx;
        Thi[o] = h; Tlo[o] = l;
    }
}

// ---------------- fused-split mma.sync GEMM: 512 thr, 2 CTAs/SM ----------------
#define ARS      160
#define BRS      80
#define A_TILE   (128*ARS)
#define B_TILE   (128*BRS)
#define STAGE_B  (A_TILE + 2*B_TILE)    // 40960
#define NSTAGE   2
__global__ __launch_bounds__(512, 2) void mma_gemm(
    const float* __restrict__ A,
    const __nv_bfloat16* __restrict__ Bhi, const __nv_bfloat16* __restrict__ Blo,
    float* __restrict__ C, int M, int N, int K)
{
    extern __shared__ __align__(16) char smem[];
    uint32_t sb = smem_u32(smem);
    int t = threadIdx.x;
    int lane = t & 31, w = t >> 5;
    int row0 = blockIdx.y * 128, col0 = blockIdx.x * 128;
    int wr = (w & 3) * 32, wn = (w >> 2) * 32;

    uint32_t aso[2]; int aqr[2], aqc[2];
#pragma unroll
    for (int i = 0; i < 2; i++) {
        int q = t + 512 * i;
        aqr[i] = q >> 3; aqc[i] = q & 7;
        aso[i] = (uint32_t)(aqr[i] * ARS + aqc[i] * 16);
    }
    int bqr = t >> 2, bqc = t & 3;
    uint32_t bso = (uint32_t)(bqr * BRS + bqc * 16);

    uint32_t a_base[2];
#pragma unroll
    for (int blk = 0; blk < 2; blk++)
        a_base[blk] = (uint32_t)((wr + blk * 16 + (lane >> 2)) * ARS + (lane & 3) * 8);

    uint32_t boff[2];
#pragma unroll
    for (int g = 0; g < 2; g++) {
        int quad = lane >> 3;
        int rB = wn + g * 16 + (lane & 7) + (quad >> 1) * 8;
        boff[g] = (uint32_t)(rB * BRS + (quad & 1) * 16);
    }

    float c[2][4][4];
#pragma unroll
    for (int i = 0; i < 2; i++)
#pragma unroll
        for (int jn = 0; jn < 4; jn++)
#pragma unroll
            for (int e = 0; e < 4; e++) c[i][jn][e] = 0.f;

    int nIter = K >> 5;

    auto load_stage = [&](int s) {
        uint32_t st = sb + (s & 1) * STAGE_B;
        int k0 = s << 5;
#pragma unroll
        for (int i = 0; i < 2; i++)
            cp_async16(st + aso[i], A + (size_t)(row0 + aqr[i]) * K + k0 + aqc[i] * 4);
        cp_async16(st + A_TILE + bso,          Bhi + (size_t)(col0 + bqr) * K + k0 + bqc * 8);
        cp_async16(st + A_TILE + B_TILE + bso, Blo + (size_t)(col0 + bqr) * K + k0 + bqc * 8);
    };

    load_stage(0); cp_commit();

    for (int it = 0; it < nIter; it++) {
        if (it + 1 < nIter) { load_stage(it + 1); cp_commit(); cp_wait1(); }
        else                { cp_wait0(); }
        __syncthreads();

        uint32_t st = sb + (it & 1) * STAGE_B;
        uint32_t sA = st, sBh = st + A_TILE, sBl = st + B_TILE + A_TILE;

#pragma unroll
        for (int j = 0; j < 2; j++) {
            uint32_t ah[2][4], al[2][4];
#pragma unroll
            for (int blk = 0; blk < 2; blk++) {
                uint32_t base = sA + a_base[blk] + j * 64;
#pragma unroll
                for (int part = 0; part < 2; part++) {
#pragma unroll
                    for (int rr = 0; rr < 2; rr++) {
                        float2 v;
                        asm volatile("ld.shared.v2.f32 {%0,%1}, [%2];"
                                     : "=f"(v.x), "=f"(v.y)
                                     : "r"(base + part * 32 + rr * (8 * ARS)));
                        int idx = part * 2 + rr;
                        splitpair(v.x, v.y, ah[blk][idx], al[blk][idx]);
                    }
                }
            }
#pragma unroll
            for (int g = 0; g < 2; g++) {
                uint32_t bh0, bh1, bh2, bh3, bl0, bl1, bl2, bl3;
                ldsm_x4(bh0, bh1, bh2, bh3, sBh + boff[g] + j * 32);
                ldsm_x4(bl0, bl1, bl2, bl3, sBl + boff[g] + j * 32);
                int n0 = g * 2, n1 = g * 2 + 1;
                // term-major: same-accumulator reuse distance = 4
                mma_bf16(c[0][n0], ah[0], bh0, bh1);
                mma_bf16(c[0][n1], ah[0], bh2, bh3);
                mma_bf16(c[1][n0], ah[1], bh0, bh1);
                mma_bf16(c[1][n1], ah[1], bh2, bh3);
                mma_bf16(c[0][n0], ah[0], bl0, bl1);
                mma_bf16(c[0][n1], ah[0], bl2, bl3);
                mma_bf16(c[1][n0], ah[1], bl0, bl1);
                mma_bf16(c[1][n1], ah[1], bl2, bl3);
                mma_bf16(c[0][n0], al[0], bh0, bh1);
                mma_bf16(c[0][n1], al[0], bh2, bh3);
                mma_bf16(c[1][n0], al[1], bh0, bh1);
                mma_bf16(c[1][n1], al[1], bh2, bh3);
            }
        }
        __syncthreads();
    }

    int rA = row0 + wr + (lane >> 2);
    int cA = col0 + wn + (lane & 3) * 2;
#pragma unroll
    for (int blk = 0; blk < 2; blk++) {
#pragma unroll
        for (int ni = 0; ni < 4; ni++) {
            float* p0 = C + (size_t)(rA + blk * 16) * N + cA + ni * 8;
            float* p1 = C + (size_t)(rA + blk * 16 + 8) * N + cA + ni * 8;
            *(float2*)p0 = make_float2(c[blk][ni][0], c[blk][ni][1]);
            *(float2*)p1 = make_float2(c[blk][ni][2], c[blk][ni][3]);
        }
    }
}

// ---------------- decode + CSR build (fused, parallel stable fill) ----------------
__global__ __launch_bounds__(256) void build_csr_k(const int* __restrict__ ei) {
    int b = blockIdx.x;
    const int* e = ei + (size_t)b * 2 * EE;
    __shared__ int sed[ESL], ses[ESL];
    __shared__ int din[NNODE], dout[NNODE];
    __shared__ int doffS[NNODE + 1], soffS[NNODE + 1];
    int t = threadIdx.x;
    for (int i = t; i < NNODE; i += 256) { din[i] = 0; dout[i] = 0; }
    __syncthreads();
    for (int i = t; i < ESL; i += 256) {
        int s, d;
        if (i < EE) { s = e[i]; d = e[EE + i]; }
        else        { s = i - EE; d = i - EE; }
        s = min(max(s, 0), NNODE - 1);
        d = min(max(d, 0), NNODE - 1);
        ses[i] = s; sed[i] = d;
        g_esrc[(size_t)b * ESL + i] = s;
        g_edst[(size_t)b * ESL + i] = d;
        atomicAdd(&dout[s], 1);
        atomicAdd(&din[d], 1);
    }
    __syncthreads();
    for (int n = t; n < NNODE; n += 256)
        g_dinv[b * NNODE + n] = rsqrtf(fmaxf((float)din[n], 1e-12f));
    if (t == 0) {
        int o = 0;
        for (int n = 0; n < NNODE; n++) { doffS[n] = o; o += din[n]; }
        doffS[NNODE] = o;
    }
    if (t == 32) {
        int o = 0;
        for (int n = 0; n < NNODE; n++) { soffS[n] = o; o += dout[n]; }
        soffS[NNODE] = o;
    }
    __syncthreads();
    for (int n = t; n <= NNODE; n += 256) {
        g_doff[b * (NNODE + 1) + n] = doffS[n];
        g_soff[b * (NNODE + 1) + n] = soffS[n];
    }
    if (t < NNODE) {
        int n = t, pos = doffS[n];
        for (int i = 0; i < ESL; i++)
            if (sed[i] == n) g_deid[(size_t)b * ESL + pos++] = i;
    } else if (t >= 128 && t < 128 + NNODE) {
        int n = t - 128, pos = soffS[n];
        for (int i = 0; i < ESL; i++)
            if (ses[i] == n) g_seid[(size_t)b * ESL + pos++] = i;
    }
}

// ---------------- wa = W_gat @ a ----------------
__global__ __launch_bounds__(256) void wa_k(const float* __restrict__ W_gat,
                                            const float* __restrict__ a_src,
                                            const float* __restrict__ a_dst) {
    int warp = threadIdx.x >> 5, lane = threadIdx.x & 31;
    for (int r = warp; r < HH; r += 8) {
        const float* wr = W_gat + (size_t)r * DD;
        float s1 = 0.f, s2 = 0.f;
        for (int j = lane; j < DD; j += 32) {
            float w = wr[j];
            s1 = fmaf(w, a_src[j], s1);
            s2 = fmaf(w, a_dst[j], s2);
        }
#pragma unroll
        for (int o = 16; o > 0; o >>= 1) {
            s1 += __shfl_xor_sync(~0u, s1, o);
            s2 += __shfl_xor_sync(~0u, s2, o);
        }
        if (lane == 0) { g_wasrc[r] = s1; g_wadst[r] = s2; }
    }
}

// ---------------- GCN aggregation + bias + relu + fused partial attproj ----------------
__global__ __launch_bounds__(256) void gcn_agg_k(const float* __restrict__ b_gcn) {
    __shared__ float sH[NNODE * 64];
    __shared__ float sW[ESL];
    __shared__ int   sSrc[ESL];
    __shared__ float sDinv[NNODE];
    int b = blockIdx.x;
    int c = blockIdx.y * 64;
    int t = threadIdx.x;
    for (int i = t; i < NNODE; i += 256) sDinv[i] = g_dinv[b * NNODE + i];
    for (int i = t; i < ESL; i += 256) {
        int eid = g_deid[(size_t)b * ESL + i];
        int s = g_esrc[(size_t)b * ESL + eid];
        sSrc[i] = s;
        sW[i] = g_dinv[b * NNODE + s];
    }
    for (int i = t; i < NNODE * 16; i += 256) {
        int n = i >> 4, j = i & 15;
        *(float4*)&sH[n * 64 + j * 4] = *(const float4*)&g_H1[(size_t)(b * NNODE + n) * HH + c + j * 4];
    }
    __syncthreads();
    int warp = t >> 5, lane = t & 31;
    float bias0 = b_gcn[c + lane * 2], bias1 = b_gcn[c + lane * 2 + 1];
    float ws0 = g_wasrc[c + lane * 2], ws1 = g_wasrc[c + lane * 2 + 1];
    float wd0 = g_wadst[c + lane * 2], wd1 = g_wadst[c + lane * 2 + 1];
    for (int n = warp; n < NNODE; n += 8) {
        float dn = sDinv[n];
        int beg = g_doff[b * (NNODE + 1) + n];
        int end = g_doff[b * (NNODE + 1) + n + 1];
        float a0 = 0.f, a1 = 0.f;
        for (int j = beg; j < end; j++) {
            int s = sSrc[j];
            float nr = sW[j] * dn;
            a0 = fmaf(nr, sH[s * 64 + lane * 2], a0);
            a1 = fmaf(nr, sH[s * 64 + lane * 2 + 1], a1);
        }
        a0 = fmaxf(a0 + bias0, 0.f);
        a1 = fmaxf(a1 + bias1, 0.f);
        size_t o = (size_t)(b * NNODE + n) * HH + c + lane * 2;
        g_h[o]     = a0;
        g_h[o + 1] = a1;
        // partial asrc/adst for this 64-col chunk
        float ps = a0 * ws0 + a1 * ws1;
        float pd = a0 * wd0 + a1 * wd1;
#pragma unroll
        for (int o2 = 16; o2 > 0; o2 >>= 1) {
            ps += __shfl_xor_sync(~0u, ps, o2);
            pd += __shfl_xor_sync(~0u, pd, o2);
        }
        if (lane == 0) {
            g_aspart[blockIdx.y * BN + b * NNODE + n] = ps;
            g_adpart[blockIdx.y * BN + b * NNODE + n] = pd;
        }
    }
}

// ---------------- reduce 8 chunk-partials -> asrc/adst (fixed order) ----------------
__global__ __launch_bounds__(256) void reduce_att_k() {
    int r = blockIdx.x * 256 + threadIdx.x;
    float s = 0.f, d = 0.f;
#pragma unroll
    for (int c = 0; c < 8; c++) {
        s += g_aspart[c * BN + r];
        d += g_adpart[c * BN + r];
    }
    g_asrc[r] = s;
    g_adst[r] = d;
}

// ---------------- GAT segment softmax + patch scores (fused) ----------------
__global__ __launch_bounds__(256) void gat_soft_scores_k() {
    __shared__ float sEv[ESL];   // asrc[src] per dst-sorted position
    __shared__ int   sEid[ESL];  // edge id per dst-sorted position
    __shared__ float sAp[ESL];   // alpha per dst-sorted position
    __shared__ float sAe[ESL];   // alpha per edge id
    __shared__ int   sSe[ESL];   // src CSR edge ids
    int b = blockIdx.x;
    int t = threadIdx.x;
    for (int i = t; i < ESL; i += 256) {
        int eid = g_deid[(size_t)b * ESL + i];
        int s = g_esrc[(size_t)b * ESL + eid];
        sEid[i] = eid;
        sEv[i] = g_asrc[b * NNODE + s];
        sSe[i] = g_seid[(size_t)b * ESL + i];
    }
    __syncthreads();
    int warp = t >> 5, lane = t & 31;
    for (int n = warp; n < NNODE; n += 8) {
        int beg = g_doff[b * (NNODE + 1) + n];
        int end = g_doff[b * (NNODE + 1) + n + 1];
        float adn = g_adst[b * NNODE + n];
        float m = -1e30f;
        for (int j = beg + lane; j < end; j += 32) {
            float ev = sEv[j] + adn;
            ev = ev >= 0.f ? ev : 0.2f * ev;
            m = fmaxf(m, ev);
        }
#pragma unroll
        for (int o = 16; o > 0; o >>= 1) m = fmaxf(m, __shfl_xor_sync(~0u, m, o));
        float sum = 0.f;
        for (int j = beg + lane; j < end; j += 32) {
            float ev = sEv[j] + adn;
            ev = ev >= 0.f ? ev : 0.2f * ev;
            sum += expf(ev - m);
        }
#pragma unroll
        for (int o = 16; o > 0; o >>= 1) sum += __shfl_xor_sync(~0u, sum, o);
        float inv = 1.f / sum;
        for (int j = beg + lane; j < end; j += 32) {
            float ev = sEv[j] + adn;
            ev = ev >= 0.f ? ev : 0.2f * ev;
            float al = expf(ev - m) * inv;
            sAp[j] = al;
            sAe[sEid[j]] = al;
            g_alpha[(size_t)b * ESL + sEid[j]] = al;
        }
    }
    __syncthreads();
    for (int n = warp; n < NNODE; n += 8) {
        int db = g_doff[b * (NNODE + 1) + n], de = g_doff[b * (NNODE + 1) + n + 1];
        int sb = g_soff[b * (NNODE + 1) + n], se = g_soff[b * (NNODE + 1) + n + 1];
        float s = 0.f;
        for (int j = db + lane; j < de; j += 32) s += sAp[j];
        for (int j = sb + lane; j < se; j += 32) s += sAe[sSe[j]];
#pragma unroll
        for (int o = 16; o > 0; o >>= 1) s += __shfl_xor_sync(~0u, s, o);
        if (lane == 0)
            g_scores[b * NNODE + n] = s / (float)((de - db) + (se - sb));
    }
}

// ---------------- top-k ----------------
__global__ __launch_bounds__(1024) void topk_k() {
    extern __shared__ float sc[];
    int t = threadIdx.x;
    for (int i = t; i < BN; i += 1024) sc[i] = g_scores[i];
    __syncthreads();
    __shared__ float bv[1024];
    __shared__ int   bi[1024];
    for (int it = 0; it < KTOP; it++) {
        float best = -1e30f; int besti = 0x7fffffff;
        for (int i = t; i < BN; i += 1024) {
            float v = sc[i];
            if (v > best || (v == best && i < besti)) { best = v; besti = i; }
        }
        bv[t] = best; bi[t] = besti;
        __syncthreads();
        for (int s = 512; s > 0; s >>= 1) {
            if (t < s) {
                float v = bv[t + s]; int i2 = bi[t + s];
                if (v > bv[t] || (v == bv[t] && i2 < bi[t])) { bv[t] = v; bi[t] = i2; }
            }
            __syncthreads();
        }
        if (t == 0) { g_topk[it] = bi[0]; sc[bi[0]] = -1e30f; }
        __syncthreads();
    }
}

// ---------------- final: aggregate(512) -> @W_gat -> +b_gat -> @W_proj ----------------
__global__ __launch_bounds__(256) void final_k(
    const float* __restrict__ W_gat, const float* __restrict__ b_gat,
    const float* __restrict__ W_proj, const float* __restrict__ b_proj,
    float* __restrict__ out)
{
    __shared__ float agg[HH];
    __shared__ float gfe[DD];
    int node = g_topk[blockIdx.x];
    int b = node / NNODE, n = node % NNODE;
    int t = threadIdx.x;

    int beg = g_doff[b * (NNODE + 1) + n];
    int end = g_doff[b * (NNODE + 1) + n + 1];
#pragma unroll
    for (int half = 0; half < 2; half++) {
        int k = t + half * 256;
        float acc = 0.f;
        for (int j = beg; j < end; j++) {
            int eid = g_deid[(size_t)b * ESL + j];
            int s = g_esrc[(size_t)b * ESL + eid];
            acc = fmaf(g_alpha[(size_t)b * ESL + eid],
                       g_h[(size_t)(b * NNODE + s) * HH + k], acc);
        }
        agg[k] = acc;
    }
    __syncthreads();

    {
        float acc = b_gat[t];
#pragma unroll 4
        for (int k = 0; k < HH; k++)
            acc = fmaf(agg[k], W_gat[(size_t)k * DD + t], acc);
        gfe[t] = acc;
    }
    __syncthreads();

    int p = t * 4;
    float4 o = *(const float4*)&b_proj[p];
#pragma unroll 4
    for (int k = 0; k < DD; k++) {
        float gv = gfe[k];
        const float4 w = *(const float4*)&W_proj[(size_t)k * PP + p];
        o.x = fmaf(gv, w.x, o.x);
        o.y = fmaf(gv, w.y, o.y);
        o.z = fmaf(gv, w.z, o.z);
        o.w = fmaf(gv, w.w, o.w);
    }
    *(float4*)&out[(size_t)blockIdx.x * PP + p] = o;
}

// ---------------- launch ----------------
extern "C" void kernel_launch(void* const* d_in, const int* in_sizes, int n_in,
                              void* d_out, int out_size)
{
    const float* x      = (const float*)d_in[0];
    const int*   ei     = (const int*)d_in[1];
    const float* W_gcn  = (const float*)d_in[2];
    const float* b_gcn  = (const float*)d_in[3];
    const float* W_gat  = (const float*)d_in[4];
    const float* b_gat  = (const float*)d_in[5];
    const float* a_src  = (const float*)d_in[6];
    const float* a_dst  = (const float*)d_in[7];
    const float* W_proj = (const float*)d_in[8];
    const float* b_proj = (const float*)d_in[9];

    __nv_bfloat16 *pW1hi, *pW1lo;
    float *pH1;
    cudaGetSymbolAddress((void**)&pW1hi, g_W1hi);
    cudaGetSymbolAddress((void**)&pW1lo, g_W1lo);
    cudaGetSymbolAddress((void**)&pH1,   g_H1);

    cudaFuncSetAttribute(mma_gemm, cudaFuncAttributeMaxDynamicSharedMemorySize, NSTAGE * STAGE_B);
    cudaFuncSetAttribute(topk_k,   cudaFuncAttributeMaxDynamicSharedMemorySize, BN * sizeof(float));

    // [0..2] prep; [3] GEMM = ncu capture slot
    splitT_k<<<dim3(FF / 32, HH / 32), dim3(32, 8)>>>(W_gcn, pW1hi, pW1lo, FF, HH);
    wa_k<<<1, 256>>>(W_gat, a_src, a_dst);
    build_csr_k<<<BB, 256>>>(ei);

    mma_gemm<<<dim3(HH / 128, BN / 128), 512, NSTAGE * STAGE_B>>>(
        x, pW1hi, pW1lo, pH1, BN, HH, FF);

    gcn_agg_k<<<dim3(BB, HH / 64), 256>>>(b_gcn);
    reduce_att_k<<<BN / 256, 256>>>();
    gat_soft_scores_k<<<BB, 256>>>();
    topk_k<<<1, 1024, BN * sizeof(float)>>>();
    final_k<<<KTOP, 256>>>(W_gat, b_gat, W_proj, b_proj, (float*)d_out);
}

// round 10
// speedup vs baseline: 1.1163x; 1.0206x over previous
#include <cuda_runtime.h>
#include <cuda_bf16.h>
#include <math.h>
#include <stdint.h>

#define BB    256
#define NNODE 100
#define EE    1600
#define ESL   1700
#define FF    2048
#define HH    512
#define DD    256
#define PP    1024
#define KTOP  50
#define BN    (BB*NNODE)   // 25600

// ---------------- scratch ----------------
__device__ __align__(16) __nv_bfloat16 g_Ahi[(size_t)BN*FF];
__device__ __align__(16) __nv_bfloat16 g_Alo[(size_t)BN*FF];
__device__ __align__(16) __nv_bfloat16 g_W1hi[(size_t)HH*FF];
__device__ __align__(16) __nv_bfloat16 g_W1lo[(size_t)HH*FF];
__device__ __align__(16) float g_H1[(size_t)BN*HH];
__device__ __align__(16) float g_h [(size_t)BN*HH];
__device__ float g_wasrc[HH];
__device__ float g_wadst[HH];
__device__ float g_dinv[BN];
__device__ float g_asrc[BN];
__device__ float g_adst[BN];
__device__ float g_aspart[8*BN];
__device__ float g_adpart[8*BN];
__device__ float g_alpha[(size_t)BB*ESL];
__device__ int   g_esrc[(size_t)BB*ESL];
__device__ int   g_edst[(size_t)BB*ESL];
__device__ int   g_doff[BB*(NNODE+1)];
__device__ int   g_soff[BB*(NNODE+1)];
__device__ int   g_deid[(size_t)BB*ESL];
__device__ int   g_seid[(size_t)BB*ESL];
__device__ float g_scores[BN];
__device__ int   g_topk[KTOP];

// ---------------- helpers ----------------
__device__ __forceinline__ uint32_t smem_u32(const void* p) {
    uint32_t a;
    asm("{ .reg .u64 t; cvta.to.shared.u64 t, %1; cvt.u32.u64 %0, t; }" : "=r"(a) : "l"(p));
    return a;
}
__device__ __forceinline__ void cp_async16(uint32_t dst, const void* src) {
    asm volatile("cp.async.cg.shared.global [%0], [%1], 16;" :: "r"(dst), "l"(src) : "memory");
}
__device__ __forceinline__ void cp_commit() {
    asm volatile("cp.async.commit_group;" ::: "memory");
}
__device__ __forceinline__ void cp_wait2() {
    asm volatile("cp.async.wait_group 2;" ::: "memory");
}
__device__ __forceinline__ void ldsm_x4(uint32_t& r0, uint32_t& r1, uint32_t& r2, uint32_t& r3, uint32_t a) {
    asm volatile("ldmatrix.sync.aligned.m8n8.x4.shared.b16 {%0,%1,%2,%3}, [%4];"
                 : "=r"(r0), "=r"(r1), "=r"(r2), "=r"(r3) : "r"(a));
}
__device__ __forceinline__ void mma_bf16(float* c, const uint32_t* a, uint32_t b0, uint32_t b1) {
    asm volatile(
        "mma.sync.aligned.m16n8k16.row.col.f32.bf16.bf16.f32 "
        "{%0,%1,%2,%3}, {%4,%5,%6,%7}, {%8,%9}, {%0,%1,%2,%3};"
        : "+f"(c[0]), "+f"(c[1]), "+f"(c[2]), "+f"(c[3])
        : "r"(a[0]), "r"(a[1]), "r"(a[2]), "r"(a[3]), "r"(b0), "r"(b1));
}
__device__ __forceinline__ void split2(float v, __nv_bfloat16& h, __nv_bfloat16& l) {
    h = __float2bfloat16_rn(v);
    l = __float2bfloat16_rn(v - __bfloat162float(h));
}

// ---------------- conversion kernels ----------------
__global__ __launch_bounds__(256) void split_x_k(const float* __restrict__ x,
                                                 __nv_bfloat16* __restrict__ hi,
                                                 __nv_bfloat16* __restrict__ lo) {
    size_t i = ((size_t)blockIdx.x * 256 + threadIdx.x) * 4;
    float4 v = *(const float4*)(x + i);
    __nv_bfloat16 h0, l0, h1, l1, h2, l2, h3, l3;
    split2(v.x, h0, l0); split2(v.y, h1, l1);
    split2(v.z, h2, l2); split2(v.w, h3, l3);
    *(__nv_bfloat162*)(hi + i)     = __nv_bfloat162(h0, h1);
    *(__nv_bfloat162*)(hi + i + 2) = __nv_bfloat162(h2, h3);
    *(__nv_bfloat162*)(lo + i)     = __nv_bfloat162(l0, l1);
    *(__nv_bfloat162*)(lo + i + 2) = __nv_bfloat162(l2, l3);
}

__global__ void splitT_k(const float* __restrict__ W, __nv_bfloat16* __restrict__ Thi,
                         __nv_bfloat16* __restrict__ Tlo, int R, int C) {
    __shared__ float tile[32][33];
    int rb = blockIdx.x * 32, cb = blockIdx.y * 32;
    int tx = threadIdx.x, ty = threadIdx.y;
#pragma unroll
    for (int i = 0; i < 4; i++)
        tile[ty + i * 8][tx] = W[(size_t)(rb + ty + i * 8) * C + cb + tx];
    __syncthreads();
#pragma unroll
    for (int i = 0; i < 4; i++) {
        float v = tile[tx][ty + i * 8];
        __nv_bfloat16 h, l; split2(v, h, l);
        size_t o = (size_t)(cb + ty + i * 8) * R + rb + tx;
        Thi[o] = h; Tlo[o] = l;
    }
}

// ---------------- mma.sync split-bf16 GEMM: 256 thr, warp 32x64, 4-stage ----------------
// All operands bf16 hi/lo, row-major [*,K], fed by ldmatrix. K-chunk 32,
// row stride 80B (conflict-free). One __syncthreads per iter (stage it+3 == it-1 mod 4).
#define RS       80
#define TILE_B   (128*RS)               // 10240
#define STAGE_B  (4*TILE_B)             // 40960: Ahi,Alo,Bhi,Blo
#define NSTAGE   4
__global__ __launch_bounds__(256) void mma_gemm(
    const __nv_bfloat16* __restrict__ Ahi, const __nv_bfloat16* __restrict__ Alo,
    const __nv_bfloat16* __restrict__ Bhi, const __nv_bfloat16* __restrict__ Blo,
    float* __restrict__ C, int M, int N, int K)
{
    extern __shared__ __align__(16) char smem[];
    uint32_t sb = smem_u32(smem);
    int t = threadIdx.x;
    int lane = t & 31, w = t >> 5;
    int row0 = blockIdx.y * 128, col0 = blockIdx.x * 128;
    int wr = (w & 3) * 32, wn = (w >> 2) * 64;

    // loader: 512 chunks per matrix (128 rows x 4x16B); 2 per thread
    uint32_t so[2]; int qr[2], qc[2];
#pragma unroll
    for (int i = 0; i < 2; i++) {
        int q = t + 256 * i;
        qr[i] = q >> 2; qc[i] = q & 3;
        so[i] = (uint32_t)(qr[i] * RS + qc[i] * 16);
    }

    // A ldmatrix offsets (16 rows x k16 per blk)
    uint32_t aoff[2];
#pragma unroll
    for (int blk = 0; blk < 2; blk++) {
        int row = wr + blk * 16 + (lane & 15);
        aoff[blk] = (uint32_t)(row * RS + (lane >> 4) * 16);
    }
    // B ldmatrix offsets (4 groups of n16)
    uint32_t boff[4];
#pragma unroll
    for (int g = 0; g < 4; g++) {
        int quad = lane >> 3;
        int rB = wn + g * 16 + (lane & 7) + (quad >> 1) * 8;
        boff[g] = (uint32_t)(rB * RS + (quad & 1) * 16);
    }

    float c[2][8][4];
#pragma unroll
    for (int i = 0; i < 2; i++)
#pragma unroll
        for (int jn = 0; jn < 8; jn++)
#pragma unroll
            for (int e = 0; e < 4; e++) c[i][jn][e] = 0.f;

    int nIter = K >> 5;
    const __nv_bfloat16* mats[4] = {Ahi, Alo, Bhi, Blo};

    auto load_stage = [&](int s) {
        uint32_t st = sb + (s & 3) * STAGE_B;
        int k0 = s << 5;
#pragma unroll
        for (int m = 0; m < 4; m++) {
            int base0 = (m < 2) ? row0 : col0;
            const __nv_bfloat16* g = mats[m];
#pragma unroll
            for (int i = 0; i < 2; i++)
                cp_async16(st + m * TILE_B + so[i], g + (size_t)(base0 + qr[i]) * K + k0 + qc[i] * 8);
        }
    };

    load_stage(0); cp_commit();
    load_stage(1); cp_commit();
    load_stage(2); cp_commit();

    for (int it = 0; it < nIter; it++) {
        cp_wait2();
        __syncthreads();

        uint32_t st = sb + (it & 3) * STAGE_B;
        uint32_t sAh = st, sAl = st + TILE_B, sBh = st + 2 * TILE_B, sBl = st + 3 * TILE_B;

#pragma unroll
        for (int j = 0; j < 2; j++) {
            uint32_t ah[2][4], al[2][4];
#pragma unroll
            for (int blk = 0; blk < 2; blk++) {
                ldsm_x4(ah[blk][0], ah[blk][1], ah[blk][2], ah[blk][3], sAh + aoff[blk] + j * 32);
                ldsm_x4(al[blk][0], al[blk][1], al[blk][2], al[blk][3], sAl + aoff[blk] + j * 32);
            }
#pragma unroll
            for (int g = 0; g < 4; g++) {
                uint32_t bh0, bh1, bh2, bh3, bl0, bl1, bl2, bl3;
                ldsm_x4(bh0, bh1, bh2, bh3, sBh + boff[g] + j * 32);
                ldsm_x4(bl0, bl1, bl2, bl3, sBl + boff[g] + j * 32);
                int n0 = g * 2, n1 = g * 2 + 1;
#pragma unroll
                for (int blk = 0; blk < 2; blk++) {
                    mma_bf16(c[blk][n0], ah[blk], bh0, bh1);
                    mma_bf16(c[blk][n1], ah[blk], bh2, bh3);
                    mma_bf16(c[blk][n0], ah[blk], bl0, bl1);
                    mma_bf16(c[blk][n1], ah[blk], bl2, bl3);
                    mma_bf16(c[blk][n0], al[blk], bh0, bh1);
                    mma_bf16(c[blk][n1], al[blk], bh2, bh3);
                }
            }
        }
        if (it + 3 < nIter) load_stage(it + 3);
        cp_commit();
    }

    int rA = row0 + wr + (lane >> 2);
    int cA = col0 + wn + (lane & 3) * 2;
#pragma unroll
    for (int blk = 0; blk < 2; blk++) {
#pragma unroll
        for (int ni = 0; ni < 8; ni++) {
            float* p0 = C + (size_t)(rA + blk * 16) * N + cA + ni * 8;
            float* p1 = C + (size_t)(rA + blk * 16 + 8) * N + cA + ni * 8;
            *(float2*)p0 = make_float2(c[blk][ni][0], c[blk][ni][1]);
            *(float2*)p1 = make_float2(c[blk][ni][2], c[blk][ni][3]);
        }
    }
}

// ---------------- decode + CSR build (fused, parallel stable fill) ----------------
__global__ __launch_bounds__(256) void build_csr_k(const int* __restrict__ ei) {
    int b = blockIdx.x;
    const int* e = ei + (size_t)b * 2 * EE;
    __shared__ int sed[ESL], ses[ESL];
    __shared__ int din[NNODE], dout[NNODE];
    __shared__ int doffS[NNODE + 1], soffS[NNODE + 1];
    int t = threadIdx.x;
    for (int i = t; i < NNODE; i += 256) { din[i] = 0; dout[i] = 0; }
    __syncthreads();
    for (int i = t; i < ESL; i += 256) {
        int s, d;
        if (i < EE) { s = e[i]; d = e[EE + i]; }
        else        { s = i - EE; d = i - EE; }
        s = min(max(s, 0), NNODE - 1);
        d = min(max(d, 0), NNODE - 1);
        ses[i] = s; sed[i] = d;
        g_esrc[(size_t)b * ESL + i] = s;
        g_edst[(size_t)b * ESL + i] = d;
        atomicAdd(&dout[s], 1);
        atomicAdd(&din[d], 1);
    }
    __syncthreads();
    for (int n = t; n < NNODE; n += 256)
        g_dinv[b * NNODE + n] = rsqrtf(fmaxf((float)din[n], 1e-12f));
    if (t == 0) {
        int o = 0;
        for (int n = 0; n < NNODE; n++) { doffS[n] = o; o += din[n]; }
        doffS[NNODE] = o;
    }
    if (t == 32) {
        int o = 0;
        for (int n = 0; n < NNODE; n++) { soffS[n] = o; o += dout[n]; }
        soffS[NNODE] = o;
    }
    __syncthreads();
    for (int n = t; n <= NNODE; n += 256) {
        g_doff[b * (NNODE + 1) + n] = doffS[n];
        g_soff[b * (NNODE + 1) + n] = soffS[n];
    }
    if (t < NNODE) {
        int n = t, pos = doffS[n];
        for (int i = 0; i < ESL; i++)
            if (sed[i] == n) g_deid[(size_t)b * ESL + pos++] = i;
    } else if (t >= 128 && t < 128 + NNODE) {
        int n = t - 128, pos = soffS[n];
        for (int i = 0; i < ESL; i++)
            if (ses[i] == n) g_seid[(size_t)b * ESL + pos++] = i;
    }
}

// ---------------- wa = W_gat @ a ----------------
__global__ __launch_bounds__(256) void wa_k(const float* __restrict__ W_gat,
                                            const float* __restrict__ a_src,
                                            const float* __restrict__ a_dst) {
    int warp = threadIdx.x >> 5, lane = threadIdx.x & 31;
    for (int r = warp; r < HH; r += 8) {
        const float* wr = W_gat + (size_t)r * DD;
        float s1 = 0.f, s2 = 0.f;
        for (int j = lane; j < DD; j += 32) {
            float w = wr[j];
            s1 = fmaf(w, a_src[j], s1);
            s2 = fmaf(w, a_dst[j], s2);
        }
#pragma unroll
        for (int o = 16; o > 0; o >>= 1) {
            s1 += __shfl_xor_sync(~0u, s1, o);
            s2 += __shfl_xor_sync(~0u, s2, o);
        }
        if (lane == 0) { g_wasrc[r] = s1; g_wadst[r] = s2; }
    }
}

// ---------------- GCN aggregation + bias + relu + fused partial attproj ----------------
__global__ __launch_bounds__(256) void gcn_agg_k(const float* __restrict__ b_gcn) {
    __shared__ float sH[NNODE * 64];
    __shared__ float sW[ESL];
    __shared__ int   sSrc[ESL];
    __shared__ float sDinv[NNODE];
    int b = blockIdx.x;
    int c = blockIdx.y * 64;
    int t = threadIdx.x;
    for (int i = t; i < NNODE; i += 256) sDinv[i] = g_dinv[b * NNODE + i];
    for (int i = t; i < ESL; i += 256) {
        int eid = g_deid[(size_t)b * ESL + i];
        int s = g_esrc[(size_t)b * ESL + eid];
        sSrc[i] = s;
        sW[i] = g_dinv[b * NNODE + s];
    }
    for (int i = t; i < NNODE * 16; i += 256) {
        int n = i >> 4, j = i & 15;
        *(float4*)&sH[n * 64 + j * 4] = *(const float4*)&g_H1[(size_t)(b * NNODE + n) * HH + c + j * 4];
    }
    __syncthreads();
    int warp = t >> 5, lane = t & 31;
    float bias0 = b_gcn[c + lane * 2], bias1 = b_gcn[c + lane * 2 + 1];
    float ws0 = g_wasrc[c + lane * 2], ws1 = g_wasrc[c + lane * 2 + 1];
    float wd0 = g_wadst[c + lane * 2], wd1 = g_wadst[c + lane * 2 + 1];
    for (int n = warp; n < NNODE; n += 8) {
        float dn = sDinv[n];
        int beg = g_doff[b * (NNODE + 1) + n];
        int end = g_doff[b * (NNODE + 1) + n + 1];
        float a0 = 0.f, a1 = 0.f;
        for (int j = beg; j < end; j++) {
            int s = sSrc[j];
            float nr = sW[j] * dn;
            a0 = fmaf(nr, sH[s * 64 + lane * 2], a0);
            a1 = fmaf(nr, sH[s * 64 + lane * 2 + 1], a1);
        }
        a0 = fmaxf(a0 + bias0, 0.f);
        a1 = fmaxf(a1 + bias1, 0.f);
        size_t o = (size_t)(b * NNODE + n) * HH + c + lane * 2;
        g_h[o]     = a0;
        g_h[o + 1] = a1;
        float ps = a0 * ws0 + a1 * ws1;
        float pd = a0 * wd0 + a1 * wd1;
#pragma unroll
        for (int o2 = 16; o2 > 0; o2 >>= 1) {
            ps += __shfl_xor_sync(~0u, ps, o2);
            pd += __shfl_xor_sync(~0u, pd, o2);
        }
        if (lane == 0) {
            g_aspart[blockIdx.y * BN + b * NNODE + n] = ps;
            g_adpart[blockIdx.y * BN + b * NNODE + n] = pd;
        }
    }
}

// ---------------- reduce 8 chunk-partials -> asrc/adst ----------------
__global__ __launch_bounds__(256) void reduce_att_k() {
    int r = blockIdx.x * 256 + threadIdx.x;
    float s = 0.f, d = 0.f;
#pragma unroll
    for (int c = 0; c < 8; c++) {
        s += g_aspart[c * BN + r];
        d += g_adpart[c * BN + r];
    }
    g_asrc[r] = s;
    g_adst[r] = d;
}

// ---------------- GAT segment softmax + patch scores (fused) ----------------
__global__ __launch_bounds__(256) void gat_soft_scores_k() {
    __shared__ float sEv[ESL];
    __shared__ int   sEid[ESL];
    __shared__ float sAp[ESL];
    __shared__ float sAe[ESL];
    __shared__ int   sSe[ESL];
    int b = blockIdx.x;
    int t = threadIdx.x;
    for (int i = t; i < ESL; i += 256) {
        int eid = g_deid[(size_t)b * ESL + i];
        int s = g_esrc[(size_t)b * ESL + eid];
        sEid[i] = eid;
        sEv[i] = g_asrc[b * NNODE + s];
        sSe[i] = g_seid[(size_t)b * ESL + i];
    }
    __syncthreads();
    int warp = t >> 5, lane = t & 31;
    for (int n = warp; n < NNODE; n += 8) {
        int beg = g_doff[b * (NNODE + 1) + n];
        int end = g_doff[b * (NNODE + 1) + n + 1];
        float adn = g_adst[b * NNODE + n];
        float m = -1e30f;
        for (int j = beg + lane; j < end; j += 32) {
            float ev = sEv[j] + adn;
            ev = ev >= 0.f ? ev : 0.2f * ev;
            m = fmaxf(m, ev);
        }
#pragma unroll
        for (int o = 16; o > 0; o >>= 1) m = fmaxf(m, __shfl_xor_sync(~0u, m, o));
        float sum = 0.f;
        for (int j = beg + lane; j < end; j += 32) {
            float ev = sEv[j] + adn;
            ev = ev >= 0.f ? ev : 0.2f * ev;
            sum += expf(ev - m);
        }
#pragma unroll
        for (int o = 16; o > 0; o >>= 1) sum += __shfl_xor_sync(~0u, sum, o);
        float inv = 1.f / sum;
        for (int j = beg + lane; j < end; j += 32) {
            float ev = sEv[j] + adn;
            ev = ev >= 0.f ? ev : 0.2f * ev;
            float al = expf(ev - m) * inv;
            sAp[j] = al;
            sAe[sEid[j]] = al;
            g_alpha[(size_t)b * ESL + sEid[j]] = al;
        }
    }
    __syncthreads();
    for (int n = warp; n < NNODE; n += 8) {
        int db = g_doff[b * (NNODE + 1) + n], de = g_doff[b * (NNODE + 1) + n + 1];
        int sb = g_soff[b * (NNODE + 1) + n], se = g_soff[b * (NNODE + 1) + n + 1];
        float s = 0.f;
        for (int j = db + lane; j < de; j += 32) s += sAp[j];
        for (int j = sb + lane; j < se; j += 32) s += sAe[sSe[j]];
#pragma unroll
        for (int o = 16; o > 0; o >>= 1) s += __shfl_xor_sync(~0u, s, o);
        if (lane == 0)
            g_scores[b * NNODE + n] = s / (float)((de - db) + (se - sb));
    }
}

// ---------------- top-k ----------------
__global__ __launch_bounds__(1024) void topk_k() {
    extern __shared__ float sc[];
    int t = threadIdx.x;
    for (int i = t; i < BN; i += 1024) sc[i] = g_scores[i];
    __syncthreads();
    __shared__ float bv[1024];
    __shared__ int   bi[1024];
    for (int it = 0; it < KTOP; it++) {
        float best = -1e30f; int besti = 0x7fffffff;
        for (int i = t; i < BN; i += 1024) {
            float v = sc[i];
            if (v > best || (v == best && i < besti)) { best = v; besti = i; }
        }
        bv[t] = best; bi[t] = besti;
        __syncthreads();
        for (int s = 512; s > 0; s >>= 1) {
            if (t < s) {
                float v = bv[t + s]; int i2 = bi[t + s];
                if (v > bv[t] || (v == bv[t] && i2 < bi[t])) { bv[t] = v; bi[t] = i2; }
            }
            __syncthreads();
        }
        if (t == 0) { g_topk[it] = bi[0]; sc[bi[0]] = -1e30f; }
        __syncthreads();
    }
}

// ---------------- final: aggregate(512) -> @W_gat -> +b_gat -> @W_proj ----------------
__global__ __launch_bounds__(256) void final_k(
    const float* __restrict__ W_gat, const float* __restrict__ b_gat,
    const float* __restrict__ W_proj, const float* __restrict__ b_proj,
    float* __restrict__ out)
{
    __shared__ float agg[HH];
    __shared__ float gfe[DD];
    int node = g_topk[blockIdx.x];
    int b = node / NNODE, n = node % NNODE;
    int t = threadIdx.x;

    int beg = g_doff[b * (NNODE + 1) + n];
    int end = g_doff[b * (NNODE + 1) + n + 1];
#pragma unroll
    for (int half = 0; half < 2; half++) {
        int k = t + half * 256;
        float acc = 0.f;
        for (int j = beg; j < end; j++) {
            int eid = g_deid[(size_t)b * ESL + j];
            int s = g_esrc[(size_t)b * ESL + eid];
            acc = fmaf(g_alpha[(size_t)b * ESL + eid],
                       g_h[(size_t)(b * NNODE + s) * HH + k], acc);
        }
        agg[k] = acc;
    }
    __syncthreads();

    {
        float acc = b_gat[t];
#pragma unroll 4
        for (int k = 0; k < HH; k++)
            acc = fmaf(agg[k], W_gat[(size_t)k * DD + t], acc);
        gfe[t] = acc;
    }
    __syncthreads();

    int p = t * 4;
    float4 o = *(const float4*)&b_proj[p];
#pragma unroll 4
    for (int k = 0; k < DD; k++) {
        float gv = gfe[k];
        const float4 w = *(const float4*)&W_proj[(size_t)k * PP + p];
        o.x = fmaf(gv, w.x, o.x);
        o.y = fmaf(gv, w.y, o.y);
        o.z = fmaf(gv, w.z, o.z);
        o.w = fmaf(gv, w.w, o.w);
    }
    *(float4*)&out[(size_t)blockIdx.x * PP + p] = o;
}

// ---------------- launch ----------------
extern "C" void kernel_launch(void* const* d_in, const int* in_sizes, int n_in,
                              void* d_out, int out_size)
{
    const float* x      = (const float*)d_in[0];
    const int*   ei     = (const int*)d_in[1];
    const float* W_gcn  = (const float*)d_in[2];
    const float* b_gcn  = (const float*)d_in[3];
    const float* W_gat  = (const float*)d_in[4];
    const float* b_gat  = (const float*)d_in[5];
    const float* a_src  = (const float*)d_in[6];
    const float* a_dst  = (const float*)d_in[7];
    const float* W_proj = (const float*)d_in[8];
    const float* b_proj = (const float*)d_in[9];

    __nv_bfloat16 *pAhi, *pAlo, *pW1hi, *pW1lo;
    float *pH1;
    cudaGetSymbolAddress((void**)&pAhi,  g_Ahi);
    cudaGetSymbolAddress((void**)&pAlo,  g_Alo);
    cudaGetSymbolAddress((void**)&pW1hi, g_W1hi);
    cudaGetSymbolAddress((void**)&pW1lo, g_W1lo);
    cudaGetSymbolAddress((void**)&pH1,   g_H1);

    cudaFuncSetAttribute(mma_gemm, cudaFuncAttributeMaxDynamicSharedMemorySize, NSTAGE * STAGE_B);
    cudaFuncSetAttribute(topk_k,   cudaFuncAttributeMaxDynamicSharedMemorySize, BN * sizeof(float));

    // [0..2] prep; [3] GEMM = ncu capture slot
    splitT_k<<<dim3(FF / 32, HH / 32), dim3(32, 8)>>>(W_gcn, pW1hi, pW1lo, FF, HH);
    split_x_k<<<(int)((size_t)BN * FF / 4 / 256), 256>>>(x, pAhi, pAlo);
    build_csr_k<<<BB, 256>>>(ei);

    mma_gemm<<<dim3(HH / 128, BN / 128), 256, NSTAGE * STAGE_B>>>(
        pAhi, pAlo, pW1hi, pW1lo, pH1, BN, HH, FF);

    wa_k<<<1, 256>>>(W_gat, a_src, a_dst);
    gcn_agg_k<<<dim3(BB, HH / 64), 256>>>(b_gcn);
    reduce_att_k<<<BN / 256, 256>>>();
    gat_soft_scores_k<<<BB, 256>>>();
    topk_k<<<1, 1024, BN * sizeof(float)>>>();
    final_k<<<KTOP, 256>>>(W_gat, b_gat, W_proj, b_proj, (float*)d_out);
}

// round 11
// speedup vs baseline: 1.1236x; 1.0066x over previous
#include <cuda_runtime.h>
#include <cuda_bf16.h>
#include <math.h>
#include <stdint.h>

#define BB    256
#define NNODE 100
#define EE    1600
#define ESL   1700
#define FF    2048
#define HH    512
#define DD    256
#define PP    1024
#define KTOP  50
#define BN    (BB*NNODE)   // 25600

// ---------------- scratch ----------------
__device__ __align__(16) __nv_bfloat16 g_Ahi[(size_t)BN*FF];
__device__ __align__(16) __nv_bfloat16 g_Alo[(size_t)BN*FF];
__device__ __align__(16) __nv_bfloat16 g_W1hi[(size_t)HH*FF];
__device__ __align__(16) __nv_bfloat16 g_W1lo[(size_t)HH*FF];
__device__ __align__(16) float g_H1[(size_t)BN*HH];
__device__ __align__(16) float g_h [(size_t)BN*HH];
__device__ float g_wasrc[HH];
__device__ float g_wadst[HH];
__device__ float g_dinv[BN];
__device__ float g_asrc[BN];
__device__ float g_adst[BN];
__device__ float g_aspart[8*BN];
__device__ float g_adpart[8*BN];
__device__ float g_alpha[(size_t)BB*ESL];
__device__ int   g_esrc[(size_t)BB*ESL];
__device__ int   g_edst[(size_t)BB*ESL];
__device__ int   g_doff[BB*(NNODE+1)];
__device__ int   g_soff[BB*(NNODE+1)];
__device__ int   g_deid[(size_t)BB*ESL];
__device__ int   g_seid[(size_t)BB*ESL];
__device__ float g_scores[BN];
__device__ int   g_topk[KTOP];

// ---------------- helpers ----------------
__device__ __forceinline__ uint32_t smem_u32(const void* p) {
    uint32_t a;
    asm("{ .reg .u64 t; cvta.to.shared.u64 t, %1; cvt.u32.u64 %0, t; }" : "=r"(a) : "l"(p));
    return a;
}
__device__ __forceinline__ void cp_async16(uint32_t dst, const void* src) {
    asm volatile("cp.async.cg.shared.global [%0], [%1], 16;" :: "r"(dst), "l"(src) : "memory");
}
__device__ __forceinline__ void cp_commit() {
    asm volatile("cp.async.commit_group;" ::: "memory");
}
__device__ __forceinline__ void cp_wait0() {
    asm volatile("cp.async.wait_group 0;" ::: "memory");
}
__device__ __forceinline__ void cp_wait1() {
    asm volatile("cp.async.wait_group 1;" ::: "memory");
}
__device__ __forceinline__ void ldsm_x4(uint32_t& r0, uint32_t& r1, uint32_t& r2, uint32_t& r3, uint32_t a) {
    asm volatile("ldmatrix.sync.aligned.m8n8.x4.shared.b16 {%0,%1,%2,%3}, [%4];"
                 : "=r"(r0), "=r"(r1), "=r"(r2), "=r"(r3) : "r"(a));
}
__device__ __forceinline__ void mma_bf16(float* c, const uint32_t* a, uint32_t b0, uint32_t b1) {
    asm volatile(
        "mma.sync.aligned.m16n8k16.row.col.f32.bf16.bf16.f32 "
        "{%0,%1,%2,%3}, {%4,%5,%6,%7}, {%8,%9}, {%0,%1,%2,%3};"
        : "+f"(c[0]), "+f"(c[1]), "+f"(c[2]), "+f"(c[3])
        : "r"(a[0]), "r"(a[1]), "r"(a[2]), "r"(a[3]), "r"(b0), "r"(b1));
}
__device__ __forceinline__ void split2(float v, __nv_bfloat16& h, __nv_bfloat16& l) {
    h = __float2bfloat16_rn(v);
    l = __float2bfloat16_rn(v - __bfloat162float(h));
}

// ---------------- conversion kernels ----------------
__global__ __launch_bounds__(256) void split_x_k(const float* __restrict__ x,
                                                 __nv_bfloat16* __restrict__ hi,
                                                 __nv_bfloat16* __restrict__ lo) {
    size_t i = ((size_t)blockIdx.x * 256 + threadIdx.x) * 4;
    float4 v = *(const float4*)(x + i);
    __nv_bfloat16 h0, l0, h1, l1, h2, l2, h3, l3;
    split2(v.x, h0, l0); split2(v.y, h1, l1);
    split2(v.z, h2, l2); split2(v.w, h3, l3);
    *(__nv_bfloat162*)(hi + i)     = __nv_bfloat162(h0, h1);
    *(__nv_bfloat162*)(hi + i + 2) = __nv_bfloat162(h2, h3);
    *(__nv_bfloat162*)(lo + i)     = __nv_bfloat162(l0, l1);
    *(__nv_bfloat162*)(lo + i + 2) = __nv_bfloat162(l2, l3);
}

__global__ void splitT_k(const float* __restrict__ W, __nv_bfloat16* __restrict__ Thi,
                         __nv_bfloat16* __restrict__ Tlo, int R, int C) {
    __shared__ float tile[32][33];
    int rb = blockIdx.x * 32, cb = blockIdx.y * 32;
    int tx = threadIdx.x, ty = threadIdx.y;
#pragma unroll
    for (int i = 0; i < 4; i++)
        tile[ty + i * 8][tx] = W[(size_t)(rb + ty + i * 8) * C + cb + tx];
    __syncthreads();
#pragma unroll
    for (int i = 0; i < 4; i++) {
        float v = tile[tx][ty + i * 8];
        __nv_bfloat16 h, l; split2(v, h, l);
        size_t o = (size_t)(cb + ty + i * 8) * R + rb + tx;
        Thi[o] = h; Tlo[o] = l;
    }
}

// ---------------- mma.sync split-bf16 GEMM: 256 thr, 2 CTAs/SM, 2-stage ----------------
// All operands bf16 hi/lo, row-major [*,K], fed by ldmatrix. K-chunk 32,
// row stride 80B. Double-buffered; two barriers/iter; partner CTA fills bubbles.
#define RS       80
#define TILE_B   (128*RS)               // 10240
#define STAGE_B  (4*TILE_B)             // 40960: Ahi,Alo,Bhi,Blo
#define NSTAGE   2
__global__ __launch_bounds__(256, 2) void mma_gemm(
    const __nv_bfloat16* __restrict__ Ahi, const __nv_bfloat16* __restrict__ Alo,
    const __nv_bfloat16* __restrict__ Bhi, const __nv_bfloat16* __restrict__ Blo,
    float* __restrict__ C, int M, int N, int K)
{
    extern __shared__ __align__(16) char smem[];
    uint32_t sb = smem_u32(smem);
    int t = threadIdx.x;
    int lane = t & 31, w = t >> 5;
    int row0 = blockIdx.y * 128, col0 = blockIdx.x * 128;
    int wr = (w & 3) * 32, wn = (w >> 2) * 64;

    // loader: 512 chunks per matrix (128 rows x 4x16B); 2 per thread
    uint32_t so[2]; int qr[2], qc[2];
#pragma unroll
    for (int i = 0; i < 2; i++) {
        int q = t + 256 * i;
        qr[i] = q >> 2; qc[i] = q & 3;
        so[i] = (uint32_t)(qr[i] * RS + qc[i] * 16);
    }

    uint32_t aoff[2];
#pragma unroll
    for (int blk = 0; blk < 2; blk++) {
        int row = wr + blk * 16 + (lane & 15);
        aoff[blk] = (uint32_t)(row * RS + (lane >> 4) * 16);
    }
    uint32_t boff[4];
#pragma unroll
    for (int g = 0; g < 4; g++) {
        int quad = lane >> 3;
        int rB = wn + g * 16 + (lane & 7) + (quad >> 1) * 8;
        boff[g] = (uint32_t)(rB * RS + (quad & 1) * 16);
    }

    float c[2][8][4];
#pragma unroll
    for (int i = 0; i < 2; i++)
#pragma unroll
        for (int jn = 0; jn < 8; jn++)
#pragma unroll
            for (int e = 0; e < 4; e++) c[i][jn][e] = 0.f;

    int nIter = K >> 5;
    const __nv_bfloat16* mats[4] = {Ahi, Alo, Bhi, Blo};

    auto load_stage = [&](int s) {
        uint32_t st = sb + (s & 1) * STAGE_B;
        int k0 = s << 5;
#pragma unroll
        for (int m = 0; m < 4; m++) {
            int base0 = (m < 2) ? row0 : col0;
            const __nv_bfloat16* g = mats[m];
#pragma unroll
            for (int i = 0; i < 2; i++)
                cp_async16(st + m * TILE_B + so[i], g + (size_t)(base0 + qr[i]) * K + k0 + qc[i] * 8);
        }
    };

    load_stage(0); cp_commit();

    for (int it = 0; it < nIter; it++) {
        if (it + 1 < nIter) { load_stage(it + 1); cp_commit(); cp_wait1(); }
        else                { cp_wait0(); }
        __syncthreads();

        uint32_t st = sb + (it & 1) * STAGE_B;
        uint32_t sAh = st, sAl = st + TILE_B, sBh = st + 2 * TILE_B, sBl = st + 3 * TILE_B;

#pragma unroll
        for (int j = 0; j < 2; j++) {
            uint32_t ah[2][4], al[2][4];
#pragma unroll
            for (int blk = 0; blk < 2; blk++) {
                ldsm_x4(ah[blk][0], ah[blk][1], ah[blk][2], ah[blk][3], sAh + aoff[blk] + j * 32);
                ldsm_x4(al[blk][0], al[blk][1], al[blk][2], al[blk][3], sAl + aoff[blk] + j * 32);
            }
#pragma unroll
            for (int g = 0; g < 4; g++) {
                uint32_t bh0, bh1, bh2, bh3, bl0, bl1, bl2, bl3;
                ldsm_x4(bh0, bh1, bh2, bh3, sBh + boff[g] + j * 32);
                ldsm_x4(bl0, bl1, bl2, bl3, sBl + boff[g] + j * 32);
                int n0 = g * 2, n1 = g * 2 + 1;
#pragma unroll
                for (int blk = 0; blk < 2; blk++) {
                    mma_bf16(c[blk][n0], ah[blk], bh0, bh1);
                    mma_bf16(c[blk][n1], ah[blk], bh2, bh3);
                    mma_bf16(c[blk][n0], ah[blk], bl0, bl1);
                    mma_bf16(c[blk][n1], ah[blk], bl2, bl3);
                    mma_bf16(c[blk][n0], al[blk], bh0, bh1);
                    mma_bf16(c[blk][n1], al[blk], bh2, bh3);
                }
            }
        }
        __syncthreads();   // WAR: next load_stage overwrites this buffer
    }

    int rA = row0 + wr + (lane >> 2);
    int cA = col0 + wn + (lane & 3) * 2;
#pragma unroll
    for (int blk = 0; blk < 2; blk++) {
#pragma unroll
        for (int ni = 0; ni < 8; ni++) {
            float* p0 = C + (size_t)(rA + blk * 16) * N + cA + ni * 8;
            float* p1 = C + (size_t)(rA + blk * 16 + 8) * N + cA + ni * 8;
            *(float2*)p0 = make_float2(c[blk][ni][0], c[blk][ni][1]);
            *(float2*)p1 = make_float2(c[blk][ni][2], c[blk][ni][3]);
        }
    }
}

// ---------------- decode + CSR build (fused, parallel stable fill) ----------------
__global__ __launch_bounds__(256) void build_csr_k(const int* __restrict__ ei) {
    int b = blockIdx.x;
    const int* e = ei + (size_t)b * 2 * EE;
    __shared__ int sed[ESL], ses[ESL];
    __shared__ int din[NNODE], dout[NNODE];
    __shared__ int doffS[NNODE + 1], soffS[NNODE + 1];
    int t = threadIdx.x;
    for (int i = t; i < NNODE; i += 256) { din[i] = 0; dout[i] = 0; }
    __syncthreads();
    for (int i = t; i < ESL; i += 256) {
        int s, d;
        if (i < EE) { s = e[i]; d = e[EE + i]; }
        else        { s = i - EE; d = i - EE; }
        s = min(max(s, 0), NNODE - 1);
        d = min(max(d, 0), NNODE - 1);
        ses[i] = s; sed[i] = d;
        g_esrc[(size_t)b * ESL + i] = s;
        g_edst[(size_t)b * ESL + i] = d;
        atomicAdd(&dout[s], 1);
        atomicAdd(&din[d], 1);
    }
    __syncthreads();
    for (int n = t; n < NNODE; n += 256)
        g_dinv[b * NNODE + n] = rsqrtf(fmaxf((float)din[n], 1e-12f));
    if (t == 0) {
        int o = 0;
        for (int n = 0; n < NNODE; n++) { doffS[n] = o; o += din[n]; }
        doffS[NNODE] = o;
    }
    if (t == 32) {
        int o = 0;
        for (int n = 0; n < NNODE; n++) { soffS[n] = o; o += dout[n]; }
        soffS[NNODE] = o;
    }
    __syncthreads();
    for (int n = t; n <= NNODE; n += 256) {
        g_doff[b * (NNODE + 1) + n] = doffS[n];
        g_soff[b * (NNODE + 1) + n] = soffS[n];
    }
    if (t < NNODE) {
        int n = t, pos = doffS[n];
        for (int i = 0; i < ESL; i++)
            if (sed[i] == n) g_deid[(size_t)b * ESL + pos++] = i;
    } else if (t >= 128 && t < 128 + NNODE) {
        int n = t - 128, pos = soffS[n];
        for (int i = 0; i < ESL; i++)
            if (ses[i] == n) g_seid[(size_t)b * ESL + pos++] = i;
    }
}

// ---------------- wa = W_gat @ a ----------------
__global__ __launch_bounds__(256) void wa_k(const float* __restrict__ W_gat,
                                            const float* __restrict__ a_src,
                                            const float* __restrict__ a_dst) {
    int warp = threadIdx.x >> 5, lane = threadIdx.x & 31;
    for (int r = warp; r < HH; r += 8) {
        const float* wr = W_gat + (size_t)r * DD;
        float s1 = 0.f, s2 = 0.f;
        for (int j = lane; j < DD; j += 32) {
            float w = wr[j];
            s1 = fmaf(w, a_src[j], s1);
            s2 = fmaf(w, a_dst[j], s2);
        }
#pragma unroll
        for (int o = 16; o > 0; o >>= 1) {
            s1 += __shfl_xor_sync(~0u, s1, o);
            s2 += __shfl_xor_sync(~0u, s2, o);
        }
        if (lane == 0) { g_wasrc[r] = s1; g_wadst[r] = s2; }
    }
}

// ---------------- GCN aggregation + bias + relu + fused partial attproj ----------------
__global__ __launch_bounds__(256) void gcn_agg_k(const float* __restrict__ b_gcn) {
    __shared__ float sH[NNODE * 64];
    __shared__ float sW[ESL];
    __shared__ int   sSrc[ESL];
    __shared__ float sDinv[NNODE];
    int b = blockIdx.x;
    int c = blockIdx.y * 64;
    int t = threadIdx.x;
    for (int i = t; i < NNODE; i += 256) sDinv[i] = g_dinv[b * NNODE + i];
    for (int i = t; i < ESL; i += 256) {
        int eid = g_deid[(size_t)b * ESL + i];
        int s = g_esrc[(size_t)b * ESL + eid];
        sSrc[i] = s;
        sW[i] = g_dinv[b * NNODE + s];
    }
    for (int i = t; i < NNODE * 16; i += 256) {
        int n = i >> 4, j = i & 15;
        *(float4*)&sH[n * 64 + j * 4] = *(const float4*)&g_H1[(size_t)(b * NNODE + n) * HH + c + j * 4];
    }
    __syncthreads();
    int warp = t >> 5, lane = t & 31;
    float bias0 = b_gcn[c + lane * 2], bias1 = b_gcn[c + lane * 2 + 1];
    float ws0 = g_wasrc[c + lane * 2], ws1 = g_wasrc[c + lane * 2 + 1];
    float wd0 = g_wadst[c + lane * 2], wd1 = g_wadst[c + lane * 2 + 1];
    for (int n = warp; n < NNODE; n += 8) {
        float dn = sDinv[n];
        int beg = g_doff[b * (NNODE + 1) + n];
        int end = g_doff[b * (NNODE + 1) + n + 1];
        float a0 = 0.f, a1 = 0.f;
        for (int j = beg; j < end; j++) {
            int s = sSrc[j];
            float nr = sW[j] * dn;
            a0 = fmaf(nr, sH[s * 64 + lane * 2], a0);
            a1 = fmaf(nr, sH[s * 64 + lane * 2 + 1], a1);
        }
        a0 = fmaxf(a0 + bias0, 0.f);
        a1 = fmaxf(a1 + bias1, 0.f);
        size_t o = (size_t)(b * NNODE + n) * HH + c + lane * 2;
        g_h[o]     = a0;
        g_h[o + 1] = a1;
        float ps = a0 * ws0 + a1 * ws1;
        float pd = a0 * wd0 + a1 * wd1;
#pragma unroll
        for (int o2 = 16; o2 > 0; o2 >>= 1) {
            ps += __shfl_xor_sync(~0u, ps, o2);
            pd += __shfl_xor_sync(~0u, pd, o2);
        }
        if (lane == 0) {
            g_aspart[blockIdx.y * BN + b * NNODE + n] = ps;
            g_adpart[blockIdx.y * BN + b * NNODE + n] = pd;
        }
    }
}

// ---------------- reduce 8 chunk-partials -> asrc/adst ----------------
__global__ __launch_bounds__(256) void reduce_att_k() {
    int r = blockIdx.x * 256 + threadIdx.x;
    float s = 0.f, d = 0.f;
#pragma unroll
    for (int c = 0; c < 8; c++) {
        s += g_aspart[c * BN + r];
        d += g_adpart[c * BN + r];
    }
    g_asrc[r] = s;
    g_adst[r] = d;
}

// ---------------- GAT segment softmax + patch scores (fused) ----------------
__global__ __launch_bounds__(256) void gat_soft_scores_k() {
    __shared__ float sEv[ESL];
    __shared__ int   sEid[ESL];
    __shared__ float sAp[ESL];
    __shared__ float sAe[ESL];
    __shared__ int   sSe[ESL];
    int b = blockIdx.x;
    int t = threadIdx.x;
    for (int i = t; i < ESL; i += 256) {
        int eid = g_deid[(size_t)b * ESL + i];
        int s = g_esrc[(size_t)b * ESL + eid];
        sEid[i] = eid;
        sEv[i] = g_asrc[b * NNODE + s];
        sSe[i] = g_seid[(size_t)b * ESL + i];
    }
    __syncthreads();
    int warp = t >> 5, lane = t & 31;
    for (int n = warp; n < NNODE; n += 8) {
        int beg = g_doff[b * (NNODE + 1) + n];
        int end = g_doff[b * (NNODE + 1) + n + 1];
        float adn = g_adst[b * NNODE + n];
        float m = -1e30f;
        for (int j = beg + lane; j < end; j += 32) {
            float ev = sEv[j] + adn;
            ev = ev >= 0.f ? ev : 0.2f * ev;
            m = fmaxf(m, ev);
        }
#pragma unroll
        for (int o = 16; o > 0; o >>= 1) m = fmaxf(m, __shfl_xor_sync(~0u, m, o));
        float sum = 0.f;
        for (int j = beg + lane; j < end; j += 32) {
            float ev = sEv[j] + adn;
            ev = ev >= 0.f ? ev : 0.2f * ev;
            sum += expf(ev - m);
        }
#pragma unroll
        for (int o = 16; o > 0; o >>= 1) sum += __shfl_xor_sync(~0u, sum, o);
        float inv = 1.f / sum;
        for (int j = beg + lane; j < end; j += 32) {
            float ev = sEv[j] + adn;
            ev = ev >= 0.f ? ev : 0.2f * ev;
            float al = expf(ev - m) * inv;
            sAp[j] = al;
            sAe[sEid[j]] = al;
            g_alpha[(size_t)b * ESL + sEid[j]] = al;
        }
    }
    __syncthreads();
    for (int n = warp; n < NNODE; n += 8) {
        int db = g_doff[b * (NNODE + 1) + n], de = g_doff[b * (NNODE + 1) + n + 1];
        int sb = g_soff[b * (NNODE + 1) + n], se = g_soff[b * (NNODE + 1) + n + 1];
        float s = 0.f;
        for (int j = db + lane; j < de; j += 32) s += sAp[j];
        for (int j = sb + lane; j < se; j += 32) s += sAe[sSe[j]];
#pragma unroll
        for (int o = 16; o > 0; o >>= 1) s += __shfl_xor_sync(~0u, s, o);
        if (lane == 0)
            g_scores[b * NNODE + n] = s / (float)((de - db) + (se - sb));
    }
}

// ---------------- top-k ----------------
__global__ __launch_bounds__(1024) void topk_k() {
    extern __shared__ float sc[];
    int t = threadIdx.x;
    for (int i = t; i < BN; i += 1024) sc[i] = g_scores[i];
    __syncthreads();
    __shared__ float bv[1024];
    __shared__ int   bi[1024];
    for (int it = 0; it < KTOP; it++) {
        float best = -1e30f; int besti = 0x7fffffff;
        for (int i = t; i < BN; i += 1024) {
            float v = sc[i];
            if (v > best || (v == best && i < besti)) { best = v; besti = i; }
        }
        bv[t] = best; bi[t] = besti;
        __syncthreads();
        for (int s = 512; s > 0; s >>= 1) {
            if (t < s) {
                float v = bv[t + s]; int i2 = bi[t + s];
                if (v > bv[t] || (v == bv[t] && i2 < bi[t])) { bv[t] = v; bi[t] = i2; }
            }
            __syncthreads();
        }
        if (t == 0) { g_topk[it] = bi[0]; sc[bi[0]] = -1e30f; }
        __syncthreads();
    }
}

// ---------------- final: aggregate(512) -> @W_gat -> +b_gat -> @W_proj ----------------
__global__ __launch_bounds__(256) void final_k(
    const float* __restrict__ W_gat, const float* __restrict__ b_gat,
    const float* __restrict__ W_proj, const float* __restrict__ b_proj,
    float* __restrict__ out)
{
    __shared__ float agg[HH];
    __shared__ float gfe[DD];
    int node = g_topk[blockIdx.x];
    int b = node / NNODE, n = node % NNODE;
    int t = threadIdx.x;

    int beg = g_doff[b * (NNODE + 1) + n];
    int end = g_doff[b * (NNODE + 1) + n + 1];
#pragma unroll
    for (int half = 0; half < 2; half++) {
        int k = t + half * 256;
        float acc = 0.f;
        for (int j = beg; j < end; j++) {
            int eid = g_deid[(size_t)b * ESL + j];
            int s = g_esrc[(size_t)b * ESL + eid];
            acc = fmaf(g_alpha[(size_t)b * ESL + eid],
                       g_h[(size_t)(b * NNODE + s) * HH + k], acc);
        }
        agg[k] = acc;
    }
    __syncthreads();

    {
        float acc = b_gat[t];
#pragma unroll 4
        for (int k = 0; k < HH; k++)
            acc = fmaf(agg[k], W_gat[(size_t)k * DD + t], acc);
        gfe[t] = acc;
    }
    __syncthreads();

    int p = t * 4;
    float4 o = *(const float4*)&b_proj[p];
#pragma unroll 4
    for (int k = 0; k < DD; k++) {
        float gv = gfe[k];
        const float4 w = *(const float4*)&W_proj[(size_t)k * PP + p];
        o.x = fmaf(gv, w.x, o.x);
        o.y = fmaf(gv, w.y, o.y);
        o.z = fmaf(gv, w.z, o.z);
        o.w = fmaf(gv, w.w, o.w);
    }
    *(float4*)&out[(size_t)blockIdx.x * PP + p] = o;
}

// ---------------- launch ----------------
extern "C" void kernel_launch(void* const* d_in, const int* in_sizes, int n_in,
                              void* d_out, int out_size)
{
    const float* x      = (const float*)d_in[0];
    const int*   ei     = (const int*)d_in[1];
    const float* W_gcn  = (const float*)d_in[2];
    const float* b_gcn  = (const float*)d_in[3];
    const float* W_gat  = (const float*)d_in[4];
    const float* b_gat  = (const float*)d_in[5];
    const float* a_src  = (const float*)d_in[6];
    const float* a_dst  = (const float*)d_in[7];
    const float* W_proj = (const float*)d_in[8];
    const float* b_proj = (const float*)d_in[9];

    __nv_bfloat16 *pAhi, *pAlo, *pW1hi, *pW1lo;
    float *pH1;
    cudaGetSymbolAddress((void**)&pAhi,  g_Ahi);
    cudaGetSymbolAddress((void**)&pAlo,  g_Alo);
    cudaGetSymbolAddress((void**)&pW1hi, g_W1hi);
    cudaGetSymbolAddress((void**)&pW1lo, g_W1lo);
    cudaGetSymbolAddress((void**)&pH1,   g_H1);

    cudaFuncSetAttribute(mma_gemm, cudaFuncAttributeMaxDynamicSharedMemorySize, NSTAGE * STAGE_B);
    cudaFuncSetAttribute(topk_k,   cudaFuncAttributeMaxDynamicSharedMemorySize, BN * sizeof(float));

    // [0..2] prep; [3] GEMM = ncu capture slot
    splitT_k<<<dim3(FF / 32, HH / 32), dim3(32, 8)>>>(W_gcn, pW1hi, pW1lo, FF, HH);
    split_x_k<<<(int)((size_t)BN * FF / 4 / 256), 256>>>(x, pAhi, pAlo);
    build_csr_k<<<BB, 256>>>(ei);

    mma_gemm<<<dim3(HH / 128, BN / 128), 256, NSTAGE * STAGE_B>>>(
        pAhi, pAlo, pW1hi, pW1lo, pH1, BN, HH, FF);

    wa_k<<<1, 256>>>(W_gat, a_src, a_dst);
    gcn_agg_k<<<dim3(BB, HH / 64), 256>>>(b_gcn);
    reduce_att_k<<<BN / 256, 256>>>();
    gat_soft_scores_k<<<BB, 256>>>();
    topk_k<<<1, 1024, BN * sizeof(float)>>>();
    final_k<<<KTOP, 256>>>(W_gat, b_gat, W_proj, b_proj, (float*)d_out);
}